// round 14
// baseline (speedup 1.0000x reference)
#include <cuda_runtime.h>
#include <cuda_bf16.h>
#include <cstdint>

#define NN 50000
#define NE 1280000
#define NG 64
#define H  64
#define NEG_BITS 0xFF800000u

// Scratch (device globals; allocation forbidden)
__device__ float g_h1[NN * H];
__device__ float g_h2[NN * H];
__device__ float g_P[NN * H];
__device__ float g_Q[NN * H];
__device__ int   g_cnt[NN + 1];      // zero at module load; scan re-zeroes each run
__device__ int   g_off[NN + 1];
__device__ int   g_bsum[128];
__device__ int   g_scan_flag;        // zero at module load; scan resets each run
__device__ int2  g_edge[NE];
__device__ __nv_bfloat16 g_WhT[2][4096];
__device__ __nv_bfloat16 g_WlT[2][4096];
__device__ __nv_bfloat16 g_W3h[8192];
__device__ __nv_bfloat16 g_W3l[8192];
__device__ float g_psum[NG * 4 * 64];
__device__ float g_pmax[NG * 4 * 64];
__device__ int   g_pcnt[NG];

__device__ __forceinline__ float lrelu(float x) { return fmaxf(x, 0.2f * x); }

__device__ __forceinline__ void atomMaxF(float* a, float v) {
    int bi = __float_as_int(v);
    if (bi == (int)0x80000000) bi = 0;
    if (bi >= 0) atomicMax((int*)a, bi);
    else         atomicMin((unsigned int*)a, (unsigned int)bi);
}

__device__ __forceinline__ uint32_t smem_u32(const void* p) {
    uint32_t a;
    asm("{ .reg .u64 t; cvta.to.shared.u64 t, %1; cvt.u32.u64 %0, t; }" : "=r"(a) : "l"(p));
    return a;
}
__device__ __forceinline__ uint32_t lds32(uint32_t a) {
    uint32_t v;
    asm volatile("ld.shared.b32 %0, [%1];" : "=r"(v) : "r"(a));
    return v;
}
__device__ __forceinline__ void sts_v2(uint32_t a, uint32_t x, uint32_t y) {
    asm volatile("st.shared.v2.b32 [%0], {%1,%2};" :: "r"(a), "r"(x), "r"(y) : "memory");
}
__device__ __forceinline__ void sts_v4(uint32_t a, uint32_t x, uint32_t y, uint32_t z, uint32_t w) {
    asm volatile("st.shared.v4.b32 [%0], {%1,%2,%3,%4};" :: "r"(a), "r"(x), "r"(y), "r"(z), "r"(w) : "memory");
}
__device__ __forceinline__ void sts_v2f(uint32_t a, float x, float y) {
    asm volatile("st.shared.v2.f32 [%0], {%1,%2};" :: "r"(a), "f"(x), "f"(y) : "memory");
}
__device__ __forceinline__ float2 lds_v2f(uint32_t a) {
    float2 v;
    asm volatile("ld.shared.v2.f32 {%0,%1}, [%2];" : "=f"(v.x), "=f"(v.y) : "r"(a));
    return v;
}
__device__ __forceinline__ uint32_t cvt2bf(float hi, float lo) {
    uint32_t r;
    asm("cvt.rn.bf16x2.f32 %0, %1, %2;" : "=r"(r) : "f"(hi), "f"(lo));
    return r;
}
__device__ __forceinline__ void ldsm_x4(uint32_t r[4], uint32_t addr) {
    asm volatile("ldmatrix.sync.aligned.m8n8.x4.shared.b16 {%0,%1,%2,%3}, [%4];"
        : "=r"(r[0]), "=r"(r[1]), "=r"(r[2]), "=r"(r[3]) : "r"(addr));
}

__device__ __forceinline__ void mma16816(float c[4], const uint32_t a[4], uint32_t b0, uint32_t b1) {
    asm volatile(
        "mma.sync.aligned.m16n8k16.row.col.f32.bf16.bf16.f32 "
        "{%0,%1,%2,%3}, {%4,%5,%6,%7}, {%8,%9}, {%0,%1,%2,%3};"
        : "+f"(c[0]), "+f"(c[1]), "+f"(c[2]), "+f"(c[3])
        : "r"(a[0]), "r"(a[1]), "r"(a[2]), "r"(a[3]), "r"(b0), "r"(b1));
}

__device__ __forceinline__ void split4(float t0, float t1, float t2, float t3,
                                       uint32_t& h0, uint32_t& h1, uint32_t& l0, uint32_t& l1) {
    h0 = cvt2bf(t1, t0);
    h1 = cvt2bf(t3, t2);
    l0 = cvt2bf(t1 - __uint_as_float(h0 & 0xFFFF0000u), t0 - __uint_as_float(h0 << 16));
    l1 = cvt2bf(t3 - __uint_as_float(h1 & 0xFFFF0000u), t2 - __uint_as_float(h1 << 16));
}

// ---------- mega-setup: init aggregates + weight preps + mlp6 + histogram ----------
// blocks: [0,3125) init h1/h2; [3125,3157) edge W split; [3157,3189) node W3 split;
//         [3189,3385) node_mlp6; [3385,8385) dst histogram (g_cnt pre-zeroed by prior run's scan).
#define SU_INIT   3125
#define SU_EW     3157
#define SU_W3     3189
#define SU_MLP6   3385
#define SU_TOTAL  8385
__global__ void setup_kernel(const float* __restrict__ W2, const float* __restrict__ W4,
                             const float* __restrict__ W3,
                             const float* __restrict__ x, const float* __restrict__ W1,
                             const float* __restrict__ b1, const int* __restrict__ dst) {
    __shared__ float sWd[6 * 64];
    __shared__ float sWq[6 * 64];
    int blk = blockIdx.x;
    int tid = threadIdx.x;
    if (blk < SU_INIT) {
        int i = blk * 256 + tid;
        float ni = __int_as_float((int)NEG_BITS);
        float4 v = make_float4(ni, ni, ni, ni);
        ((float4*)g_h1)[i] = v;
        ((float4*)g_h2)[i] = v;
    } else if (blk < SU_EW) {
        int i = (blk - SU_INIT) * 256 + tid;
        int c = i >> 12, idx = i & 4095;
        const float* W = c ? W4 : W2;
        int n = idx >> 6, j = idx & 63;
        float w = W[j * 64 + n];
        __nv_bfloat16 h = __float2bfloat16_rn(w);
        g_WhT[c][idx] = h;
        g_WlT[c][idx] = __float2bfloat16_rn(w - __bfloat162float(h));
    } else if (blk < SU_W3) {
        int i = (blk - SU_EW) * 256 + tid;
        int n = i >> 6, j = i & 63;
        float w;
        if (n < 64) w = W3[j * 64 + n] - W3[(64 + j) * 64 + n];
        else        w = W3[(64 + j) * 64 + (n - 64)];
        __nv_bfloat16 h = __float2bfloat16_rn(w);
        g_W3h[i] = h;
        g_W3l[i] = __float2bfloat16_rn(w - __bfloat162float(h));
    } else if (blk < SU_MLP6) {
        for (int i = tid; i < 6 * 64; i += 256) {
            float wb = W1[6 * 64 + i];
            sWd[i] = W1[i] - wb;
            sWq[i] = wb;
        }
        __syncthreads();
        int n = (blk - SU_W3) * 256 + tid;
        if (n < NN) {
            float xr[6];
#pragma unroll
            for (int j = 0; j < 6; j++) xr[j] = x[(size_t)n * 6 + j];
            float* Pp = g_P + (size_t)n * 64;
            float* Qp = g_Q + (size_t)n * 64;
#pragma unroll 4
            for (int k = 0; k < 64; k++) {
                float p = __ldg(b1 + k), q = 0.f;
#pragma unroll
                for (int j = 0; j < 6; j++) {
                    p = fmaf(xr[j], sWd[j * 64 + k], p);
                    q = fmaf(xr[j], sWq[j * 64 + k], q);
                }
                Pp[k] = p;
                Qp[k] = q;
            }
        }
    } else {
        int e = (blk - SU_MLP6) * 256 + tid;
        if (e < NE) atomicAdd(&g_cnt[dst[e]], 1);
    }
}

// ---------- fused scan: per-block scan + last-block top scan; re-zeroes g_cnt ----------
#define NBLK_SCAN 98
__global__ void scan_kernel() {
    int tid = threadIdx.x;
    int i = blockIdx.x * 512 + tid;
    int v = 0;
    if (i < NN) {
        v = g_cnt[i];
        g_cnt[i] = 0;           // restore invariant for next run
    }
    int lane = tid & 31, wid = tid >> 5;
    int x = v;
#pragma unroll
    for (int o = 1; o < 32; o <<= 1) {
        int y = __shfl_up_sync(0xffffffffu, x, o);
        if (lane >= o) x += y;
    }
    __shared__ int ws[16];
    if (lane == 31) ws[wid] = x;
    __syncthreads();
    if (wid == 0 && lane < 16) {
        int y = ws[lane];
#pragma unroll
        for (int o = 1; o < 16; o <<= 1) {
            int z = __shfl_up_sync(0xffffu, y, o);
            if (lane >= o) y += z;
        }
        ws[lane] = y;
    }
    __syncthreads();
    int base = wid ? ws[wid - 1] : 0;
    if (i < NN) g_off[i] = base + x - v;
    if (tid == 511) g_bsum[blockIdx.x] = base + x;

    __threadfence();
    __shared__ int lastBlk;
    if (tid == 0) lastBlk = (atomicAdd(&g_scan_flag, 1) == (int)gridDim.x - 1) ? 1 : 0;
    __syncthreads();
    if (!lastBlk) return;

    __shared__ int s[128];
    if (tid < 128) s[tid] = (tid < NBLK_SCAN) ? g_bsum[tid] : 0;
    __syncthreads();
    for (int o = 1; o < 128; o <<= 1) {
        int vv = (tid >= o && tid < 128) ? s[tid - o] : 0;
        __syncthreads();
        if (tid < 128) s[tid] += vv;
        __syncthreads();
    }
    if (tid < NBLK_SCAN) g_bsum[tid] = (tid == 0) ? 0 : s[tid - 1];
    if (tid == 0) g_scan_flag = 0;
}

__global__ void scatter_kernel(const int* __restrict__ src, const int* __restrict__ dst) {
    int e = blockIdx.x * blockDim.x + threadIdx.x;
    if (e >= NE) return;
    int d = dst[e];
    int pos = atomicAdd(&g_off[d], 1) + g_bsum[d >> 9];
    g_edge[pos] = make_int2(src[e], d);
}

// Conv2 node GEMM on tensor cores, cooperative A gather.
__global__ __launch_bounds__(128)
void node_mlp64_mma(const float* __restrict__ b3, const float* __restrict__ b2) {
    extern __shared__ char dsm_raw[];
    uint32_t base = smem_u32(dsm_raw);
    uint32_t sAh = base;
    uint32_t sAl = base + 16384;
    uint32_t sBh = base + 32768;
    uint32_t sBl = base + 49152;

    int tid = threadIdx.x;
    int wid = tid >> 5, lane = tid & 31;
    int gq = lane >> 2, tq = lane & 3;

    const uint4* Bh128 = (const uint4*)g_W3h;
    const uint4* Bl128 = (const uint4*)g_W3l;
#pragma unroll
    for (int it = 0; it < 8; it++) {
        int ch = tid + it * 128;
        int n = ch >> 3, jc = ch & 7;
        uint32_t off = (uint32_t)(n * 128) + ((((uint32_t)jc << 4)) ^ ((uint32_t)(n & 7) << 4));
        uint4 vh = Bh128[ch], vl = Bl128[ch];
        sts_v4(sBh + off, vh.x, vh.y, vh.z, vh.w);
        sts_v4(sBl + off, vl.x, vl.y, vl.z, vl.w);
    }

    {
        int part = lane & 15, half = lane >> 4;
        int tilebase = blockIdx.x * 128;
        float4 bb = __ldg(((const float4*)b2) + part);
#pragma unroll
        for (int i = 0; i < 16; i++) {
            int lr = (wid << 5) + 2 * i + half;
            int node = tilebase + lr;
            int cn = node < NN ? node : NN - 1;
            float4 v = ((const float4*)(g_h1 + (size_t)cn * 64))[part];
            float t0 = (__float_as_int(v.x) == (int)NEG_BITS) ? 0.f : lrelu(v.x + bb.x);
            float t1 = (__float_as_int(v.y) == (int)NEG_BITS) ? 0.f : lrelu(v.y + bb.y);
            float t2 = (__float_as_int(v.z) == (int)NEG_BITS) ? 0.f : lrelu(v.z + bb.z);
            float t3 = (__float_as_int(v.w) == (int)NEG_BITS) ? 0.f : lrelu(v.w + bb.w);
            uint32_t h0, h1, l0, l1;
            split4(t0, t1, t2, t3, h0, h1, l0, l1);
            uint32_t addr = (uint32_t)(lr * 128) + (((uint32_t)(part * 8)) ^ ((uint32_t)(lr & 7) << 4));
            sts_v2(sAh + addr, h0, h1);
            sts_v2(sAl + addr, l0, l1);
        }
    }
    __syncthreads();

    float acc[2][16][4];
#pragma unroll
    for (int nt = 0; nt < 16; nt++) {
        int col = nt * 8 + tq * 2;
        float b0 = 0.f, b1 = 0.f;
        if (col < 64) { b0 = __ldg(b3 + col); b1 = __ldg(b3 + col + 1); }
#pragma unroll
        for (int mt = 0; mt < 2; mt++) {
            acc[mt][nt][0] = b0; acc[mt][nt][1] = b1;
            acc[mt][nt][2] = b0; acc[mt][nt][3] = b1;
        }
    }

#pragma unroll
    for (int kt = 0; kt < 4; kt++) {
        uint32_t cb = (uint32_t)(kt * 32 + tq * 4);
        uint32_t ah[2][4], al[2][4];
#pragma unroll
        for (int mt = 0; mt < 2; mt++) {
            int r0 = wid * 32 + mt * 16 + gq;
            uint32_t xr = (uint32_t)(r0 & 7) << 4;
            uint32_t c0 = cb ^ xr, c1 = (cb + 16) ^ xr;
            uint32_t b0 = (uint32_t)(r0 * 128), b1 = b0 + 1024;
            ah[mt][0] = lds32(sAh + b0 + c0); ah[mt][1] = lds32(sAh + b1 + c0);
            ah[mt][2] = lds32(sAh + b0 + c1); ah[mt][3] = lds32(sAh + b1 + c1);
            al[mt][0] = lds32(sAl + b0 + c0); al[mt][1] = lds32(sAl + b1 + c0);
            al[mt][2] = lds32(sAl + b0 + c1); al[mt][3] = lds32(sAl + b1 + c1);
        }
        uint32_t xb = (uint32_t)gq << 4;
        uint32_t cb0 = cb ^ xb, cb1 = (cb + 16) ^ xb;
#pragma unroll
        for (int nt = 0; nt < 16; nt++) {
            uint32_t rb = (uint32_t)((nt * 8 + gq) * 128);
            uint32_t bh0 = lds32(sBh + rb + cb0), bh1 = lds32(sBh + rb + cb1);
            uint32_t bl0 = lds32(sBl + rb + cb0), bl1 = lds32(sBl + rb + cb1);
#pragma unroll
            for (int mt = 0; mt < 2; mt++) {
                mma16816(acc[mt][nt], ah[mt], bh0, bh1);
                mma16816(acc[mt][nt], ah[mt], bl0, bl1);
                mma16816(acc[mt][nt], al[mt], bh0, bh1);
            }
        }
    }

    int tilebase = blockIdx.x * 128;
#pragma unroll
    for (int mt = 0; mt < 2; mt++) {
        int r0 = wid * 32 + mt * 16 + gq;
        int n0 = tilebase + r0, n1 = n0 + 8;
#pragma unroll
        for (int nt = 0; nt < 16; nt++) {
            int col = nt * 8 + tq * 2;
            float* basep = (col < 64) ? g_P : g_Q;
            int c = col & 63;
            if (n0 < NN)
                *(float2*)(basep + (size_t)n0 * 64 + c) = make_float2(acc[mt][nt][0], acc[mt][nt][1]);
            if (n1 < NN)
                *(float2*)(basep + (size_t)n1 * 64 + c) = make_float2(acc[mt][nt][2], acc[mt][nt][3]);
        }
    }
}

// ---------- mma.sync edge kernel: 256-edge tiles, cooperative gather, ldmatrix ----------
template <int PASS>
__global__ __launch_bounds__(256, 2)
void edge_mma_kernel() {
    extern __shared__ char dsm_raw[];
    uint32_t base = smem_u32(dsm_raw);
    uint32_t sAh = base;
    uint32_t sAl = base + 32768;
    uint32_t sBh = base + 65536;
    uint32_t sBl = base + 73728;
    int* sDst = (int*)(dsm_raw + 81920);
    int* sSrc = (int*)(dsm_raw + 82944);

    int tid = threadIdx.x;
    int wid = tid >> 5, lane = tid & 31;
    int tq = lane & 3;

    const uint4* Bh128 = (const uint4*)g_WhT[PASS - 1];
    const uint4* Bl128 = (const uint4*)g_WlT[PASS - 1];
#pragma unroll
    for (int it = 0; it < 2; it++) {
        int ch = tid + it * 256;
        int n = ch >> 3, jc = ch & 7;
        uint32_t off = (uint32_t)(n * 128) + ((((uint32_t)jc << 4)) ^ ((uint32_t)(n & 7) << 4));
        uint4 vh = Bh128[ch], vl = Bl128[ch];
        sts_v4(sBh + off, vh.x, vh.y, vh.z, vh.w);
        sts_v4(sBl + off, vl.x, vl.y, vl.z, vl.w);
    }

    int e = blockIdx.x * 256 + tid;
    int2 sd = g_edge[e];
    sSrc[tid] = sd.x;
    sDst[tid] = sd.y;
    __syncwarp();

    {
        int part = lane & 15, half = lane >> 4;
#pragma unroll
        for (int i = 0; i < 16; i++) {
            int le = (wid << 5) + 2 * i + half;
            int dd = sDst[le], ss = sSrc[le];
            float4 p = ((const float4*)(g_P + (size_t)dd * 64))[part];
            float4 q = ((const float4*)(g_Q + (size_t)ss * 64))[part];
            float t0 = lrelu(p.x + q.x), t1 = lrelu(p.y + q.y);
            float t2 = lrelu(p.z + q.z), t3 = lrelu(p.w + q.w);
            uint32_t h0, h1, l0, l1;
            split4(t0, t1, t2, t3, h0, h1, l0, l1);
            uint32_t addr = (uint32_t)(le * 128) + (((uint32_t)(part * 8)) ^ ((uint32_t)(le & 7) << 4));
            sts_v2(sAh + addr, h0, h1);
            sts_v2(sAl + addr, l0, l1);
        }
    }
    __syncthreads();

    float acc[2][8][4];
#pragma unroll
    for (int mt = 0; mt < 2; mt++)
#pragma unroll
        for (int nt = 0; nt < 8; nt++)
#pragma unroll
            for (int r = 0; r < 4; r++) acc[mt][nt][r] = 0.f;

    int l8 = lane & 7, mface = lane >> 3;
    uint32_t colp = (uint32_t)(mface >> 1) * 16;
    int rsel = (mface & 1) * 8 + l8;
    uint32_t aBase[2], aX[2];
#pragma unroll
    for (int mt = 0; mt < 2; mt++) {
        int r = wid * 32 + mt * 16 + rsel;
        aBase[mt] = (uint32_t)(r * 128);
        aX[mt] = (uint32_t)(r & 7) << 4;
    }
    uint32_t bBase[4], bX[4];
#pragma unroll
    for (int p = 0; p < 4; p++) {
        int n = p * 16 + rsel;
        bBase[p] = (uint32_t)(n * 128);
        bX[p] = (uint32_t)(n & 7) << 4;
    }

#pragma unroll
    for (int kt = 0; kt < 4; kt++) {
        uint32_t kb = (uint32_t)(kt * 32) + colp;
        uint32_t ah[2][4], al[2][4];
#pragma unroll
        for (int mt = 0; mt < 2; mt++) {
            uint32_t off = kb ^ aX[mt];
            ldsm_x4(ah[mt], sAh + aBase[mt] + off);
            ldsm_x4(al[mt], sAl + aBase[mt] + off);
        }
#pragma unroll
        for (int p = 0; p < 4; p++) {
            uint32_t off = kb ^ bX[p];
            uint32_t bh[4], bl[4];
            ldsm_x4(bh, sBh + bBase[p] + off);
            ldsm_x4(bl, sBl + bBase[p] + off);
#pragma unroll
            for (int mt = 0; mt < 2; mt++) {
                mma16816(acc[mt][2 * p],     ah[mt], bh[0], bh[2]);
                mma16816(acc[mt][2 * p],     ah[mt], bl[0], bl[2]);
                mma16816(acc[mt][2 * p],     al[mt], bh[0], bh[2]);
                mma16816(acc[mt][2 * p + 1], ah[mt], bh[1], bh[3]);
                mma16816(acc[mt][2 * p + 1], ah[mt], bl[1], bl[3]);
                mma16816(acc[mt][2 * p + 1], al[mt], bh[1], bh[3]);
            }
        }
    }

    __syncthreads();
    uint32_t sD = base;
    int gq = lane >> 2;
#pragma unroll
    for (int mt = 0; mt < 2; mt++) {
        int row0 = wid * 32 + mt * 16 + gq;
        uint32_t xd = (uint32_t)(row0 & 7) << 5;
        uint32_t rb0 = (uint32_t)(row0 * 256), rb1 = rb0 + 2048;
#pragma unroll
        for (int nt = 0; nt < 8; nt++) {
            uint32_t cby = (uint32_t)((nt * 8 + tq * 2) * 4) ^ xd;
            sts_v2f(sD + rb0 + cby, acc[mt][nt][0], acc[mt][nt][1]);
            sts_v2f(sD + rb1 + cby, acc[mt][nt][2], acc[mt][nt][3]);
        }
    }
    __syncthreads();

    int cp = tid & 31, seg = tid >> 5;
    int e0 = seg * 32;
    float* agg = (PASS == 1) ? g_h1 : g_h2;
    uint32_t cb2 = (uint32_t)cp * 8;
    int curd = sDst[e0];
    float2 mx = lds_v2f(sD + (uint32_t)(e0 * 256) + (cb2 ^ ((uint32_t)(e0 & 7) << 5)));
#pragma unroll
    for (int k = 1; k < 32; k++) {
        int ee = e0 + k;
        int de = sDst[ee];
        float2 v = lds_v2f(sD + (uint32_t)(ee * 256) + (cb2 ^ ((uint32_t)(ee & 7) << 5)));
        if (de != curd) {
            atomMaxF(agg + (size_t)curd * 64 + 2 * cp, mx.x);
            atomMaxF(agg + (size_t)curd * 64 + 2 * cp + 1, mx.y);
            curd = de;
            mx = v;
        } else {
            mx.x = fmaxf(mx.x, v.x);
            mx.y = fmaxf(mx.y, v.y);
        }
    }
    atomMaxF(agg + (size_t)curd * 64 + 2 * cp, mx.x);
    atomMaxF(agg + (size_t)curd * 64 + 2 * cp + 1, mx.y);
}

// ---------- pooling / classifier ----------
__global__ void pool_kernel(const int* __restrict__ batch, const float* __restrict__ bprev) {
    int g = blockIdx.x, q = blockIdx.y;
    int lo = 0, hi = NN;
    while (lo < hi) { int m = (lo + hi) >> 1; if (batch[m] < g) lo = m + 1; else hi = m; }
    int start = lo;
    hi = NN;
    while (lo < hi) { int m = (lo + hi) >> 1; if (batch[m] <= g) lo = m + 1; else hi = m; }
    int end = lo;
    int len = end - start;
    int qs = start + (len * q) / 4;
    int qe = start + (len * (q + 1)) / 4;

    int tid = threadIdx.x;
    int k = tid & 63, grp = tid >> 6;
    float bk = __ldg(bprev + k);
    float s = 0.f;
    float mx = -3.0e38f;
    for (int n = qs + grp; n < qe; n += 4) {
        float z = g_h2[(size_t)n * H + k];
        float v = (__float_as_int(z) == (int)NEG_BITS) ? 0.f : lrelu(z + bk);
        s += v;
        mx = fmaxf(mx, v);
    }
    __shared__ float ss[256], sm[256];
    ss[tid] = s; sm[tid] = mx;
    __syncthreads();
    if (grp == 0) {
        s += ss[64 + k] + ss[128 + k] + ss[192 + k];
        mx = fmaxf(fmaxf(mx, sm[64 + k]), fmaxf(sm[128 + k], sm[192 + k]));
        g_psum[(g * 4 + q) * 64 + k] = s;
        g_pmax[(g * 4 + q) * 64 + k] = mx;
    }
    if (q == 0 && tid == 0) g_pcnt[g] = len;
}

__global__ void cls_kernel(const float* __restrict__ Wc1, const float* __restrict__ bc1,
                           const float* __restrict__ Wc2, const float* __restrict__ bc2,
                           float* __restrict__ out) {
    int g = blockIdx.x, t = threadIdx.x;
    __shared__ float gv[128];
    int cnt = g_pcnt[g];
    {
        float s = g_psum[(g * 4 + 0) * 64 + t] + g_psum[(g * 4 + 1) * 64 + t]
                + g_psum[(g * 4 + 2) * 64 + t] + g_psum[(g * 4 + 3) * 64 + t];
        float m = fmaxf(fmaxf(g_pmax[(g * 4 + 0) * 64 + t], g_pmax[(g * 4 + 1) * 64 + t]),
                        fmaxf(g_pmax[(g * 4 + 2) * 64 + t], g_pmax[(g * 4 + 3) * 64 + t]));
        gv[t] = s / (float)(cnt > 1 ? cnt : 1);
        gv[t + 64] = (cnt > 0) ? m : 0.f;
    }
    __syncthreads();
    float acc = __ldg(bc1 + t);
#pragma unroll 8
    for (int j = 0; j < 128; j++) acc = fmaf(gv[j], Wc1[j * 64 + t], acc);
    float v = lrelu(acc) * __ldg(Wc2 + t);
#pragma unroll
    for (int o = 16; o > 0; o >>= 1) v += __shfl_down_sync(0xffffffffu, v, o);
    __shared__ float part[2];
    if ((t & 31) == 0) part[t >> 5] = v;
    __syncthreads();
    if (t == 0) out[g] = part[0] + part[1] + __ldg(bc2);
}

extern "C" void kernel_launch(void* const* d_in, const int* in_sizes, int n_in,
                              void* d_out, int out_size) {
    const float* x    = (const float*)d_in[0];
    const int*   ei   = (const int*)d_in[1];
    const int*   batch= (const int*)d_in[2];
    const float* W1   = (const float*)d_in[3];
    const float* b1   = (const float*)d_in[4];
    const float* W2   = (const float*)d_in[5];
    const float* b2   = (const float*)d_in[6];
    const float* W3   = (const float*)d_in[7];
    const float* b3   = (const float*)d_in[8];
    const float* W4   = (const float*)d_in[9];
    const float* b4   = (const float*)d_in[10];
    const float* Wc1  = (const float*)d_in[11];
    const float* bc1  = (const float*)d_in[12];
    const float* Wc2  = (const float*)d_in[13];
    const float* bc2  = (const float*)d_in[14];
    float* out = (float*)d_out;

    const int* src = ei;
    const int* dst = ei + NE;

    const int DSM_E = 83968;
    const int DSM_N = 65536;
    cudaFuncSetAttribute(edge_mma_kernel<1>, cudaFuncAttributeMaxDynamicSharedMemorySize, DSM_E);
    cudaFuncSetAttribute(edge_mma_kernel<2>, cudaFuncAttributeMaxDynamicSharedMemorySize, DSM_E);
    cudaFuncSetAttribute(node_mlp64_mma, cudaFuncAttributeMaxDynamicSharedMemorySize, DSM_N);

    setup_kernel<<<SU_TOTAL, 256>>>(W2, W4, W3, x, W1, b1, dst);
    scan_kernel<<<NBLK_SCAN, 512>>>();
    scatter_kernel<<<(NE + 255) / 256, 256>>>(src, dst);
    edge_mma_kernel<1><<<NE / 256, 256, DSM_E>>>();
    node_mlp64_mma<<<(NN + 127) / 128, 128, DSM_N>>>(b3, b2);
    edge_mma_kernel<2><<<NE / 256, 256, DSM_E>>>();
    pool_kernel<<<dim3(NG, 4), 256>>>(batch, b4);
    cls_kernel<<<NG, 64>>>(Wc1, bc1, Wc2, bc2, out);
}

// round 15
// speedup vs baseline: 1.2148x; 1.2148x over previous
#include <cuda_runtime.h>
#include <cuda_bf16.h>
#include <cstdint>

#define NN 50000
#define NE 1280000
#define NG 64
#define H  64
#define NEG_BITS 0xFF800000u

// Scratch (device globals; allocation forbidden)
__device__ float g_h1[NN * H];
__device__ float g_h2[NN * H];
__device__ float g_P[NN * H];
__device__ float g_Q[NN * H];
__device__ int   g_cnt[NN + 1];
__device__ int   g_off[NN + 1];
__device__ int   g_bsum[128];
__device__ int2  g_edge[NE];
__device__ __nv_bfloat16 g_WhT[2][4096];
__device__ __nv_bfloat16 g_WlT[2][4096];
__device__ __nv_bfloat16 g_W3h[8192];
__device__ __nv_bfloat16 g_W3l[8192];
__device__ float g_psum[NG * 4 * 64];
__device__ float g_pmax[NG * 4 * 64];
__device__ int   g_pcnt[NG];

__device__ __forceinline__ float lrelu(float x) { return fmaxf(x, 0.2f * x); }

__device__ __forceinline__ void atomMaxF(float* a, float v) {
    int bi = __float_as_int(v);
    if (bi == (int)0x80000000) bi = 0;
    if (bi >= 0) atomicMax((int*)a, bi);
    else         atomicMin((unsigned int*)a, (unsigned int)bi);
}

__device__ __forceinline__ uint32_t smem_u32(const void* p) {
    uint32_t a;
    asm("{ .reg .u64 t; cvta.to.shared.u64 t, %1; cvt.u32.u64 %0, t; }" : "=r"(a) : "l"(p));
    return a;
}
__device__ __forceinline__ uint32_t lds32(uint32_t a) {
    uint32_t v;
    asm volatile("ld.shared.b32 %0, [%1];" : "=r"(v) : "r"(a));
    return v;
}
__device__ __forceinline__ void sts_v2(uint32_t a, uint32_t x, uint32_t y) {
    asm volatile("st.shared.v2.b32 [%0], {%1,%2};" :: "r"(a), "r"(x), "r"(y) : "memory");
}
__device__ __forceinline__ void sts_v4(uint32_t a, uint32_t x, uint32_t y, uint32_t z, uint32_t w) {
    asm volatile("st.shared.v4.b32 [%0], {%1,%2,%3,%4};" :: "r"(a), "r"(x), "r"(y), "r"(z), "r"(w) : "memory");
}
__device__ __forceinline__ void sts_v2f(uint32_t a, float x, float y) {
    asm volatile("st.shared.v2.f32 [%0], {%1,%2};" :: "r"(a), "f"(x), "f"(y) : "memory");
}
__device__ __forceinline__ float2 lds_v2f(uint32_t a) {
    float2 v;
    asm volatile("ld.shared.v2.f32 {%0,%1}, [%2];" : "=f"(v.x), "=f"(v.y) : "r"(a));
    return v;
}
__device__ __forceinline__ uint32_t cvt2bf(float hi, float lo) {
    uint32_t r;
    asm("cvt.rn.bf16x2.f32 %0, %1, %2;" : "=r"(r) : "f"(hi), "f"(lo));
    return r;
}
__device__ __forceinline__ void ldsm_x4(uint32_t r[4], uint32_t addr) {
    asm volatile("ldmatrix.sync.aligned.m8n8.x4.shared.b16 {%0,%1,%2,%3}, [%4];"
        : "=r"(r[0]), "=r"(r[1]), "=r"(r[2]), "=r"(r[3]) : "r"(addr));
}

__device__ __forceinline__ void mma16816(float c[4], const uint32_t a[4], uint32_t b0, uint32_t b1) {
    asm volatile(
        "mma.sync.aligned.m16n8k16.row.col.f32.bf16.bf16.f32 "
        "{%0,%1,%2,%3}, {%4,%5,%6,%7}, {%8,%9}, {%0,%1,%2,%3};"
        : "+f"(c[0]), "+f"(c[1]), "+f"(c[2]), "+f"(c[3])
        : "r"(a[0]), "r"(a[1]), "r"(a[2]), "r"(a[3]), "r"(b0), "r"(b1));
}

__device__ __forceinline__ void split4(float t0, float t1, float t2, float t3,
                                       uint32_t& h0, uint32_t& h1, uint32_t& l0, uint32_t& l1) {
    h0 = cvt2bf(t1, t0);
    h1 = cvt2bf(t3, t2);
    l0 = cvt2bf(t1 - __uint_as_float(h0 & 0xFFFF0000u), t0 - __uint_as_float(h0 << 16));
    l1 = cvt2bf(t3 - __uint_as_float(h1 & 0xFFFF0000u), t2 - __uint_as_float(h1 << 16));
}

// ---------- fused setup ----------
__global__ void setup_kernel(const float* __restrict__ W2, const float* __restrict__ W4,
                             const float* __restrict__ W3) {
    int blk = blockIdx.x;
    if (blk < 3125) {
        int i = blk * 256 + threadIdx.x;
        float ni = __int_as_float((int)NEG_BITS);
        float4 v = make_float4(ni, ni, ni, ni);
        if (i < NN * H / 4) {
            ((float4*)g_h1)[i] = v;
            ((float4*)g_h2)[i] = v;
        }
        if (i <= NN) g_cnt[i] = 0;
    } else if (blk < 3157) {
        int i = (blk - 3125) * 256 + threadIdx.x;
        int c = i >> 12, idx = i & 4095;
        const float* W = c ? W4 : W2;
        int n = idx >> 6, j = idx & 63;
        float w = W[j * 64 + n];
        __nv_bfloat16 h = __float2bfloat16_rn(w);
        g_WhT[c][idx] = h;
        g_WlT[c][idx] = __float2bfloat16_rn(w - __bfloat162float(h));
    } else {
        int i = (blk - 3157) * 256 + threadIdx.x;
        int n = i >> 6, j = i & 63;
        float w;
        if (n < 64) w = W3[j * 64 + n] - W3[(64 + j) * 64 + n];
        else        w = W3[(64 + j) * 64 + (n - 64)];
        __nv_bfloat16 h = __float2bfloat16_rn(w);
        g_W3h[i] = h;
        g_W3l[i] = __float2bfloat16_rn(w - __bfloat162float(h));
    }
}

__global__ void hist_kernel(const int* __restrict__ dst) {
    int e = blockIdx.x * blockDim.x + threadIdx.x;
    if (e < NE) atomicAdd(&g_cnt[dst[e]], 1);
}

__global__ void bscan_kernel() {
    int tid = threadIdx.x;
    int i = blockIdx.x * 512 + tid;
    int v = (i < NN) ? g_cnt[i] : 0;
    int lane = tid & 31, wid = tid >> 5;
    int x = v;
#pragma unroll
    for (int o = 1; o < 32; o <<= 1) {
        int y = __shfl_up_sync(0xffffffffu, x, o);
        if (lane >= o) x += y;
    }
    __shared__ int ws[16];
    if (lane == 31) ws[wid] = x;
    __syncthreads();
    if (wid == 0 && lane < 16) {
        int y = ws[lane];
#pragma unroll
        for (int o = 1; o < 16; o <<= 1) {
            int z = __shfl_up_sync(0xffffu, y, o);
            if (lane >= o) y += z;
        }
        ws[lane] = y;
    }
    __syncthreads();
    int base = wid ? ws[wid - 1] : 0;
    if (i < NN) g_off[i] = base + x - v;
    if (tid == 511) g_bsum[blockIdx.x] = base + x;
}

__global__ void topscan_kernel(int nb) {
    __shared__ int s[128];
    int t = threadIdx.x;
    s[t] = (t < nb) ? g_bsum[t] : 0;
    __syncthreads();
    for (int o = 1; o < 128; o <<= 1) {
        int v = (t >= o) ? s[t - o] : 0;
        __syncthreads();
        s[t] += v;
        __syncthreads();
    }
    if (t < nb) g_bsum[t] = (t == 0) ? 0 : s[t - 1];
}

__global__ void scatter_kernel(const int* __restrict__ src, const int* __restrict__ dst) {
    int e = blockIdx.x * blockDim.x + threadIdx.x;
    if (e >= NE) return;
    int d = dst[e];
    int pos = atomicAdd(&g_off[d], 1) + g_bsum[d >> 9];
    g_edge[pos] = make_int2(src[e], d);
}

// ---------- node MLPs ----------
__global__ __launch_bounds__(128)
void node_mlp6(const float* __restrict__ x, const float* __restrict__ W,
               const float* __restrict__ b) {
    __shared__ float sWd[6 * 64];
    __shared__ float sWq[6 * 64];
    int tid = threadIdx.x;
    for (int i = tid; i < 6 * 64; i += 128) {
        float wb = W[6 * 64 + i];
        sWd[i] = W[i] - wb;
        sWq[i] = wb;
    }
    __syncthreads();
    int n = blockIdx.x * 128 + tid;
    if (n >= NN) return;
    float xr[6];
#pragma unroll
    for (int j = 0; j < 6; j++) xr[j] = x[(size_t)n * 6 + j];
    float* Pp = g_P + (size_t)n * 64;
    float* Qp = g_Q + (size_t)n * 64;
#pragma unroll 4
    for (int k = 0; k < 64; k++) {
        float p = __ldg(b + k), q = 0.f;
#pragma unroll
        for (int j = 0; j < 6; j++) {
            p = fmaf(xr[j], sWd[j * 64 + k], p);
            q = fmaf(xr[j], sWq[j * 64 + k], q);
        }
        Pp[k] = p;
        Qp[k] = q;
    }
}

// Conv2 node GEMM on tensor cores, cooperative A gather.
__global__ __launch_bounds__(128)
void node_mlp64_mma(const float* __restrict__ b3, const float* __restrict__ b2) {
    extern __shared__ char dsm_raw[];
    uint32_t base = smem_u32(dsm_raw);
    uint32_t sAh = base;
    uint32_t sAl = base + 16384;
    uint32_t sBh = base + 32768;
    uint32_t sBl = base + 49152;

    int tid = threadIdx.x;
    int wid = tid >> 5, lane = tid & 31;
    int gq = lane >> 2, tq = lane & 3;

    const uint4* Bh128 = (const uint4*)g_W3h;
    const uint4* Bl128 = (const uint4*)g_W3l;
#pragma unroll
    for (int it = 0; it < 8; it++) {
        int ch = tid + it * 128;
        int n = ch >> 3, jc = ch & 7;
        uint32_t off = (uint32_t)(n * 128) + ((((uint32_t)jc << 4)) ^ ((uint32_t)(n & 7) << 4));
        uint4 vh = Bh128[ch], vl = Bl128[ch];
        sts_v4(sBh + off, vh.x, vh.y, vh.z, vh.w);
        sts_v4(sBl + off, vl.x, vl.y, vl.z, vl.w);
    }

    {
        int part = lane & 15, half = lane >> 4;
        int tilebase = blockIdx.x * 128;
        float4 bb = __ldg(((const float4*)b2) + part);
#pragma unroll
        for (int i = 0; i < 16; i++) {
            int lr = (wid << 5) + 2 * i + half;
            int node = tilebase + lr;
            int cn = node < NN ? node : NN - 1;
            float4 v = ((const float4*)(g_h1 + (size_t)cn * 64))[part];
            float t0 = (__float_as_int(v.x) == (int)NEG_BITS) ? 0.f : lrelu(v.x + bb.x);
            float t1 = (__float_as_int(v.y) == (int)NEG_BITS) ? 0.f : lrelu(v.y + bb.y);
            float t2 = (__float_as_int(v.z) == (int)NEG_BITS) ? 0.f : lrelu(v.z + bb.z);
            float t3 = (__float_as_int(v.w) == (int)NEG_BITS) ? 0.f : lrelu(v.w + bb.w);
            uint32_t h0, h1, l0, l1;
            split4(t0, t1, t2, t3, h0, h1, l0, l1);
            uint32_t addr = (uint32_t)(lr * 128) + (((uint32_t)(part * 8)) ^ ((uint32_t)(lr & 7) << 4));
            sts_v2(sAh + addr, h0, h1);
            sts_v2(sAl + addr, l0, l1);
        }
    }
    __syncthreads();

    float acc[2][16][4];
#pragma unroll
    for (int nt = 0; nt < 16; nt++) {
        int col = nt * 8 + tq * 2;
        float b0 = 0.f, b1 = 0.f;
        if (col < 64) { b0 = __ldg(b3 + col); b1 = __ldg(b3 + col + 1); }
#pragma unroll
        for (int mt = 0; mt < 2; mt++) {
            acc[mt][nt][0] = b0; acc[mt][nt][1] = b1;
            acc[mt][nt][2] = b0; acc[mt][nt][3] = b1;
        }
    }

#pragma unroll
    for (int kt = 0; kt < 4; kt++) {
        uint32_t cb = (uint32_t)(kt * 32 + tq * 4);
        uint32_t ah[2][4], al[2][4];
#pragma unroll
        for (int mt = 0; mt < 2; mt++) {
            int r0 = wid * 32 + mt * 16 + gq;
            uint32_t xr = (uint32_t)(r0 & 7) << 4;
            uint32_t c0 = cb ^ xr, c1 = (cb + 16) ^ xr;
            uint32_t b0 = (uint32_t)(r0 * 128), b1 = b0 + 1024;
            ah[mt][0] = lds32(sAh + b0 + c0); ah[mt][1] = lds32(sAh + b1 + c0);
            ah[mt][2] = lds32(sAh + b0 + c1); ah[mt][3] = lds32(sAh + b1 + c1);
            al[mt][0] = lds32(sAl + b0 + c0); al[mt][1] = lds32(sAl + b1 + c0);
            al[mt][2] = lds32(sAl + b0 + c1); al[mt][3] = lds32(sAl + b1 + c1);
        }
        uint32_t xb = (uint32_t)gq << 4;
        uint32_t cb0 = cb ^ xb, cb1 = (cb + 16) ^ xb;
#pragma unroll
        for (int nt = 0; nt < 16; nt++) {
            uint32_t rb = (uint32_t)((nt * 8 + gq) * 128);
            uint32_t bh0 = lds32(sBh + rb + cb0), bh1 = lds32(sBh + rb + cb1);
            uint32_t bl0 = lds32(sBl + rb + cb0), bl1 = lds32(sBl + rb + cb1);
#pragma unroll
            for (int mt = 0; mt < 2; mt++) {
                mma16816(acc[mt][nt], ah[mt], bh0, bh1);
                mma16816(acc[mt][nt], ah[mt], bl0, bl1);
                mma16816(acc[mt][nt], al[mt], bh0, bh1);
            }
        }
    }

    int tilebase = blockIdx.x * 128;
#pragma unroll
    for (int mt = 0; mt < 2; mt++) {
        int r0 = wid * 32 + mt * 16 + gq;
        int n0 = tilebase + r0, n1 = n0 + 8;
#pragma unroll
        for (int nt = 0; nt < 16; nt++) {
            int col = nt * 8 + tq * 2;
            float* basep = (col < 64) ? g_P : g_Q;
            int c = col & 63;
            if (n0 < NN)
                *(float2*)(basep + (size_t)n0 * 64 + c) = make_float2(acc[mt][nt][0], acc[mt][nt][1]);
            if (n1 < NN)
                *(float2*)(basep + (size_t)n1 * 64 + c) = make_float2(acc[mt][nt][2], acc[mt][nt][3]);
        }
    }
}

// ---------- mma.sync edge kernel: 256-edge tiles, shfl-indexed gather, ldmatrix ----------
// Smem: Ah[0,32K) Al[32K,64K) Bh[64K,72K) Bl[72K,80K). D (fp32) reuses [0,64K).
template <int PASS>
__global__ __launch_bounds__(256, 2)
void edge_mma_kernel() {
    extern __shared__ char dsm_raw[];
    uint32_t base = smem_u32(dsm_raw);
    uint32_t sAh = base;
    uint32_t sAl = base + 32768;
    uint32_t sBh = base + 65536;
    uint32_t sBl = base + 73728;

    int tid = threadIdx.x;
    int wid = tid >> 5, lane = tid & 31;
    int tq = lane & 3;

    // Own edge (loaded first so LDG is in flight during B staging)
    int e = blockIdx.x * 256 + tid;
    int2 sd = g_edge[e];

    // Stage B (vectorized)
    const uint4* Bh128 = (const uint4*)g_WhT[PASS - 1];
    const uint4* Bl128 = (const uint4*)g_WlT[PASS - 1];
#pragma unroll
    for (int it = 0; it < 2; it++) {
        int ch = tid + it * 256;
        int n = ch >> 3, jc = ch & 7;
        uint32_t off = (uint32_t)(n * 128) + ((((uint32_t)jc << 4)) ^ ((uint32_t)(n & 7) << 4));
        uint4 vh = Bh128[ch], vl = Bl128[ch];
        sts_v4(sBh + off, vh.x, vh.y, vh.z, vh.w);
        sts_v4(sBl + off, vl.x, vl.y, vl.z, vl.w);
    }

    // Cooperative A gather: indices via warp shuffle (warp owns edges [wid*32, wid*32+32))
    {
        int part = lane & 15, half = lane >> 4;
#pragma unroll
        for (int i = 0; i < 16; i++) {
            int lk = 2 * i + half;                        // lane holding this edge
            int dd = __shfl_sync(0xffffffffu, sd.y, lk);
            int ss = __shfl_sync(0xffffffffu, sd.x, lk);
            float4 p = ((const float4*)(g_P + (size_t)dd * 64))[part];
            float4 q = ((const float4*)(g_Q + (size_t)ss * 64))[part];
            float t0 = lrelu(p.x + q.x), t1 = lrelu(p.y + q.y);
            float t2 = lrelu(p.z + q.z), t3 = lrelu(p.w + q.w);
            uint32_t h0, h1, l0, l1;
            split4(t0, t1, t2, t3, h0, h1, l0, l1);
            int le = (wid << 5) + lk;
            uint32_t addr = (uint32_t)(le * 128) + (((uint32_t)(part * 8)) ^ ((uint32_t)(le & 7) << 4));
            sts_v2(sAh + addr, h0, h1);
            sts_v2(sAl + addr, l0, l1);
        }
    }
    __syncthreads();

    float acc[2][8][4];
#pragma unroll
    for (int mt = 0; mt < 2; mt++)
#pragma unroll
        for (int nt = 0; nt < 8; nt++)
#pragma unroll
            for (int r = 0; r < 4; r++) acc[mt][nt][r] = 0.f;

    int l8 = lane & 7, mface = lane >> 3;
    uint32_t colp = (uint32_t)(mface >> 1) * 16;
    int rsel = (mface & 1) * 8 + l8;
    uint32_t aBase[2], aX[2];
#pragma unroll
    for (int mt = 0; mt < 2; mt++) {
        int r = wid * 32 + mt * 16 + rsel;
        aBase[mt] = (uint32_t)(r * 128);
        aX[mt] = (uint32_t)(r & 7) << 4;
    }
    uint32_t bBase[4], bX[4];
#pragma unroll
    for (int p = 0; p < 4; p++) {
        int n = p * 16 + rsel;
        bBase[p] = (uint32_t)(n * 128);
        bX[p] = (uint32_t)(n & 7) << 4;
    }

#pragma unroll
    for (int kt = 0; kt < 4; kt++) {
        uint32_t kb = (uint32_t)(kt * 32) + colp;
        uint32_t ah[2][4], al[2][4];
#pragma unroll
        for (int mt = 0; mt < 2; mt++) {
            uint32_t off = kb ^ aX[mt];
            ldsm_x4(ah[mt], sAh + aBase[mt] + off);
            ldsm_x4(al[mt], sAl + aBase[mt] + off);
        }
#pragma unroll
        for (int p = 0; p < 4; p++) {
            uint32_t off = kb ^ bX[p];
            uint32_t bh[4], bl[4];
            ldsm_x4(bh, sBh + bBase[p] + off);
            ldsm_x4(bl, sBl + bBase[p] + off);
#pragma unroll
            for (int mt = 0; mt < 2; mt++) {
                mma16816(acc[mt][2 * p],     ah[mt], bh[0], bh[2]);
                mma16816(acc[mt][2 * p],     ah[mt], bl[0], bl[2]);
                mma16816(acc[mt][2 * p],     al[mt], bh[0], bh[2]);
                mma16816(acc[mt][2 * p + 1], ah[mt], bh[1], bh[3]);
                mma16816(acc[mt][2 * p + 1], ah[mt], bl[1], bl[3]);
                mma16816(acc[mt][2 * p + 1], al[mt], bh[1], bh[3]);
            }
        }
    }

    __syncthreads();
    uint32_t sD = base;
    int gq = lane >> 2;
#pragma unroll
    for (int mt = 0; mt < 2; mt++) {
        int row0 = wid * 32 + mt * 16 + gq;
        uint32_t xd = (uint32_t)(row0 & 7) << 5;
        uint32_t rb0 = (uint32_t)(row0 * 256), rb1 = rb0 + 2048;
#pragma unroll
        for (int nt = 0; nt < 8; nt++) {
            uint32_t cby = (uint32_t)((nt * 8 + tq * 2) * 4) ^ xd;
            sts_v2f(sD + rb0 + cby, acc[mt][nt][0], acc[mt][nt][1]);
            sts_v2f(sD + rb1 + cby, acc[mt][nt][2], acc[mt][nt][3]);
        }
    }
    __syncthreads();

    // Epilogue: thread owns channel pair cp over own warp's 32 edges.
    // dst values come from warp shuffles of sd.y; loads batched 8 at a time.
    int cp = lane;
    int e0 = wid * 32;
    float* agg = (PASS == 1) ? g_h1 : g_h2;
    uint32_t cb2 = (uint32_t)cp * 8;
    int curd = __shfl_sync(0xffffffffu, sd.y, 0);
    float2 mx = make_float2(-3.0e38f, -3.0e38f);
#pragma unroll
    for (int b = 0; b < 4; b++) {
        int dd[8];
        float2 v[8];
#pragma unroll
        for (int j = 0; j < 8; j++) {
            int k = b * 8 + j;
            dd[j] = __shfl_sync(0xffffffffu, sd.y, k);
            int ee = e0 + k;
            v[j] = lds_v2f(sD + (uint32_t)(ee * 256) + (cb2 ^ ((uint32_t)(ee & 7) << 5)));
        }
#pragma unroll
        for (int j = 0; j < 8; j++) {
            if (dd[j] != curd) {
                atomMaxF(agg + (size_t)curd * 64 + 2 * cp, mx.x);
                atomMaxF(agg + (size_t)curd * 64 + 2 * cp + 1, mx.y);
                curd = dd[j];
                mx = v[j];
            } else {
                mx.x = fmaxf(mx.x, v[j].x);
                mx.y = fmaxf(mx.y, v[j].y);
            }
        }
    }
    atomMaxF(agg + (size_t)curd * 64 + 2 * cp, mx.x);
    atomMaxF(agg + (size_t)curd * 64 + 2 * cp + 1, mx.y);
}

// ---------- pooling / classifier ----------
__global__ void pool_kernel(const int* __restrict__ batch, const float* __restrict__ bprev) {
    int g = blockIdx.x, q = blockIdx.y;
    int lo = 0, hi = NN;
    while (lo < hi) { int m = (lo + hi) >> 1; if (batch[m] < g) lo = m + 1; else hi = m; }
    int start = lo;
    hi = NN;
    while (lo < hi) { int m = (lo + hi) >> 1; if (batch[m] <= g) lo = m + 1; else hi = m; }
    int end = lo;
    int len = end - start;
    int qs = start + (len * q) / 4;
    int qe = start + (len * (q + 1)) / 4;

    int tid = threadIdx.x;
    int k = tid & 63, grp = tid >> 6;
    float bk = __ldg(bprev + k);
    float s = 0.f;
    float mx = -3.0e38f;
    for (int n = qs + grp; n < qe; n += 4) {
        float z = g_h2[(size_t)n * H + k];
        float v = (__float_as_int(z) == (int)NEG_BITS) ? 0.f : lrelu(z + bk);
        s += v;
        mx = fmaxf(mx, v);
    }
    __shared__ float ss[256], sm[256];
    ss[tid] = s; sm[tid] = mx;
    __syncthreads();
    if (grp == 0) {
        s += ss[64 + k] + ss[128 + k] + ss[192 + k];
        mx = fmaxf(fmaxf(mx, sm[64 + k]), fmaxf(sm[128 + k], sm[192 + k]));
        g_psum[(g * 4 + q) * 64 + k] = s;
        g_pmax[(g * 4 + q) * 64 + k] = mx;
    }
    if (q == 0 && tid == 0) g_pcnt[g] = len;
}

__global__ void cls_kernel(const float* __restrict__ Wc1, const float* __restrict__ bc1,
                           const float* __restrict__ Wc2, const float* __restrict__ bc2,
                           float* __restrict__ out) {
    int g = blockIdx.x, t = threadIdx.x;
    __shared__ float gv[128];
    int cnt = g_pcnt[g];
    {
        float s = g_psum[(g * 4 + 0) * 64 + t] + g_psum[(g * 4 + 1) * 64 + t]
                + g_psum[(g * 4 + 2) * 64 + t] + g_psum[(g * 4 + 3) * 64 + t];
        float m = fmaxf(fmaxf(g_pmax[(g * 4 + 0) * 64 + t], g_pmax[(g * 4 + 1) * 64 + t]),
                        fmaxf(g_pmax[(g * 4 + 2) * 64 + t], g_pmax[(g * 4 + 3) * 64 + t]));
        gv[t] = s / (float)(cnt > 1 ? cnt : 1);
        gv[t + 64] = (cnt > 0) ? m : 0.f;
    }
    __syncthreads();
    float acc = __ldg(bc1 + t);
#pragma unroll 8
    for (int j = 0; j < 128; j++) acc = fmaf(gv[j], Wc1[j * 64 + t], acc);
    float v = lrelu(acc) * __ldg(Wc2 + t);
#pragma unroll
    for (int o = 16; o > 0; o >>= 1) v += __shfl_down_sync(0xffffffffu, v, o);
    __shared__ float part[2];
    if ((t & 31) == 0) part[t >> 5] = v;
    __syncthreads();
    if (t == 0) out[g] = part[0] + part[1] + __ldg(bc2);
}

extern "C" void kernel_launch(void* const* d_in, const int* in_sizes, int n_in,
                              void* d_out, int out_size) {
    const float* x    = (const float*)d_in[0];
    const int*   ei   = (const int*)d_in[1];
    const int*   batch= (const int*)d_in[2];
    const float* W1   = (const float*)d_in[3];
    const float* b1   = (const float*)d_in[4];
    const float* W2   = (const float*)d_in[5];
    const float* b2   = (const float*)d_in[6];
    const float* W3   = (const float*)d_in[7];
    const float* b3   = (const float*)d_in[8];
    const float* W4   = (const float*)d_in[9];
    const float* b4   = (const float*)d_in[10];
    const float* Wc1  = (const float*)d_in[11];
    const float* bc1  = (const float*)d_in[12];
    const float* Wc2  = (const float*)d_in[13];
    const float* bc2  = (const float*)d_in[14];
    float* out = (float*)d_out;

    const int* src = ei;
    const int* dst = ei + NE;

    const int DSM_E = 81920;   // A 64K + B 16K
    const int DSM_N = 65536;
    cudaFuncSetAttribute(edge_mma_kernel<1>, cudaFuncAttributeMaxDynamicSharedMemorySize, DSM_E);
    cudaFuncSetAttribute(edge_mma_kernel<2>, cudaFuncAttributeMaxDynamicSharedMemorySize, DSM_E);
    cudaFuncSetAttribute(node_mlp64_mma, cudaFuncAttributeMaxDynamicSharedMemorySize, DSM_N);

    const int NB = (NN + 511) / 512;   // 98
    setup_kernel<<<3189, 256>>>(W2, W4, W3);
    hist_kernel<<<(NE + 255) / 256, 256>>>(dst);
    bscan_kernel<<<NB, 512>>>();
    topscan_kernel<<<1, 128>>>(NB);
    scatter_kernel<<<(NE + 255) / 256, 256>>>(src, dst);
    node_mlp6<<<(NN + 127) / 128, 128>>>(x, W1, b1);
    edge_mma_kernel<1><<<NE / 256, 256, DSM_E>>>();
    node_mlp64_mma<<<(NN + 127) / 128, 128, DSM_N>>>(b3, b2);
    edge_mma_kernel<2><<<NE / 256, 256, DSM_E>>>();
    pool_kernel<<<dim3(NG, 4), 256>>>(batch, b4);
    cls_kernel<<<NG, 64>>>(Wc1, bc1, Wc2, bc2, out);
}

// round 16
// speedup vs baseline: 1.2218x; 1.0057x over previous
#include <cuda_runtime.h>
#include <cuda_bf16.h>
#include <cstdint>

#define NN 50000
#define NE 1280000
#define NG 64
#define H  64
#define NEG_BITS 0xFF800000u
#define NCHUNK (NE / 32)       // 40000 32-edge chunks
#define NCTA_E 304             // persistent CTAs (2 per SM on GB300)

// Scratch (device globals; allocation forbidden)
__device__ float g_h1[NN * H];
__device__ float g_h2[NN * H];
__device__ float g_P[NN * H];
__device__ float g_Q[NN * H];
__device__ int   g_cnt[NN + 1];
__device__ int   g_off[NN + 1];
__device__ int   g_bsum[128];
__device__ int2  g_edge[NE];
__device__ __nv_bfloat16 g_WhT[2][4096];
__device__ __nv_bfloat16 g_WlT[2][4096];
__device__ __nv_bfloat16 g_W3h[8192];
__device__ __nv_bfloat16 g_W3l[8192];
__device__ float g_psum[NG * 4 * 64];
__device__ float g_pmax[NG * 4 * 64];
__device__ int   g_pcnt[NG];

__device__ __forceinline__ float lrelu(float x) { return fmaxf(x, 0.2f * x); }

__device__ __forceinline__ void atomMaxF(float* a, float v) {
    int bi = __float_as_int(v);
    if (bi == (int)0x80000000) bi = 0;
    if (bi >= 0) atomicMax((int*)a, bi);
    else         atomicMin((unsigned int*)a, (unsigned int)bi);
}

__device__ __forceinline__ uint32_t smem_u32(const void* p) {
    uint32_t a;
    asm("{ .reg .u64 t; cvta.to.shared.u64 t, %1; cvt.u32.u64 %0, t; }" : "=r"(a) : "l"(p));
    return a;
}
__device__ __forceinline__ uint32_t lds32(uint32_t a) {
    uint32_t v;
    asm volatile("ld.shared.b32 %0, [%1];" : "=r"(v) : "r"(a));
    return v;
}
__device__ __forceinline__ void sts_v2(uint32_t a, uint32_t x, uint32_t y) {
    asm volatile("st.shared.v2.b32 [%0], {%1,%2};" :: "r"(a), "r"(x), "r"(y) : "memory");
}
__device__ __forceinline__ void sts_v4(uint32_t a, uint32_t x, uint32_t y, uint32_t z, uint32_t w) {
    asm volatile("st.shared.v4.b32 [%0], {%1,%2,%3,%4};" :: "r"(a), "r"(x), "r"(y), "r"(z), "r"(w) : "memory");
}
__device__ __forceinline__ void sts_v2f(uint32_t a, float x, float y) {
    asm volatile("st.shared.v2.f32 [%0], {%1,%2};" :: "r"(a), "f"(x), "f"(y) : "memory");
}
__device__ __forceinline__ float2 lds_v2f(uint32_t a) {
    float2 v;
    asm volatile("ld.shared.v2.f32 {%0,%1}, [%2];" : "=f"(v.x), "=f"(v.y) : "r"(a));
    return v;
}
__device__ __forceinline__ uint32_t cvt2bf(float hi, float lo) {
    uint32_t r;
    asm("cvt.rn.bf16x2.f32 %0, %1, %2;" : "=r"(r) : "f"(hi), "f"(lo));
    return r;
}
__device__ __forceinline__ void ldsm_x4(uint32_t r[4], uint32_t addr) {
    asm volatile("ldmatrix.sync.aligned.m8n8.x4.shared.b16 {%0,%1,%2,%3}, [%4];"
        : "=r"(r[0]), "=r"(r[1]), "=r"(r[2]), "=r"(r[3]) : "r"(addr));
}

__device__ __forceinline__ void mma16816(float c[4], const uint32_t a[4], uint32_t b0, uint32_t b1) {
    asm volatile(
        "mma.sync.aligned.m16n8k16.row.col.f32.bf16.bf16.f32 "
        "{%0,%1,%2,%3}, {%4,%5,%6,%7}, {%8,%9}, {%0,%1,%2,%3};"
        : "+f"(c[0]), "+f"(c[1]), "+f"(c[2]), "+f"(c[3])
        : "r"(a[0]), "r"(a[1]), "r"(a[2]), "r"(a[3]), "r"(b0), "r"(b1));
}

__device__ __forceinline__ void split4(float t0, float t1, float t2, float t3,
                                       uint32_t& h0, uint32_t& h1, uint32_t& l0, uint32_t& l1) {
    h0 = cvt2bf(t1, t0);
    h1 = cvt2bf(t3, t2);
    l0 = cvt2bf(t1 - __uint_as_float(h0 & 0xFFFF0000u), t0 - __uint_as_float(h0 << 16));
    l1 = cvt2bf(t3 - __uint_as_float(h1 & 0xFFFF0000u), t2 - __uint_as_float(h1 << 16));
}

// ---------- fused setup ----------
__global__ void setup_kernel(const float* __restrict__ W2, const float* __restrict__ W4,
                             const float* __restrict__ W3) {
    int blk = blockIdx.x;
    if (blk < 3125) {
        int i = blk * 256 + threadIdx.x;
        float ni = __int_as_float((int)NEG_BITS);
        float4 v = make_float4(ni, ni, ni, ni);
        if (i < NN * H / 4) {
            ((float4*)g_h1)[i] = v;
            ((float4*)g_h2)[i] = v;
        }
        if (i <= NN) g_cnt[i] = 0;
    } else if (blk < 3157) {
        int i = (blk - 3125) * 256 + threadIdx.x;
        int c = i >> 12, idx = i & 4095;
        const float* W = c ? W4 : W2;
        int n = idx >> 6, j = idx & 63;
        float w = W[j * 64 + n];
        __nv_bfloat16 h = __float2bfloat16_rn(w);
        g_WhT[c][idx] = h;
        g_WlT[c][idx] = __float2bfloat16_rn(w - __bfloat162float(h));
    } else {
        int i = (blk - 3157) * 256 + threadIdx.x;
        int n = i >> 6, j = i & 63;
        float w;
        if (n < 64) w = W3[j * 64 + n] - W3[(64 + j) * 64 + n];
        else        w = W3[(64 + j) * 64 + (n - 64)];
        __nv_bfloat16 h = __float2bfloat16_rn(w);
        g_W3h[i] = h;
        g_W3l[i] = __float2bfloat16_rn(w - __bfloat162float(h));
    }
}

__global__ void hist_kernel(const int* __restrict__ dst) {
    int e = blockIdx.x * blockDim.x + threadIdx.x;
    if (e < NE) atomicAdd(&g_cnt[dst[e]], 1);
}

__global__ void bscan_kernel() {
    int tid = threadIdx.x;
    int i = blockIdx.x * 512 + tid;
    int v = (i < NN) ? g_cnt[i] : 0;
    int lane = tid & 31, wid = tid >> 5;
    int x = v;
#pragma unroll
    for (int o = 1; o < 32; o <<= 1) {
        int y = __shfl_up_sync(0xffffffffu, x, o);
        if (lane >= o) x += y;
    }
    __shared__ int ws[16];
    if (lane == 31) ws[wid] = x;
    __syncthreads();
    if (wid == 0 && lane < 16) {
        int y = ws[lane];
#pragma unroll
        for (int o = 1; o < 16; o <<= 1) {
            int z = __shfl_up_sync(0xffffu, y, o);
            if (lane >= o) y += z;
        }
        ws[lane] = y;
    }
    __syncthreads();
    int base = wid ? ws[wid - 1] : 0;
    if (i < NN) g_off[i] = base + x - v;
    if (tid == 511) g_bsum[blockIdx.x] = base + x;
}

__global__ void topscan_kernel(int nb) {
    __shared__ int s[128];
    int t = threadIdx.x;
    s[t] = (t < nb) ? g_bsum[t] : 0;
    __syncthreads();
    for (int o = 1; o < 128; o <<= 1) {
        int v = (t >= o) ? s[t - o] : 0;
        __syncthreads();
        s[t] += v;
        __syncthreads();
    }
    if (t < nb) g_bsum[t] = (t == 0) ? 0 : s[t - 1];
}

__global__ void scatter_kernel(const int* __restrict__ src, const int* __restrict__ dst) {
    int e = blockIdx.x * blockDim.x + threadIdx.x;
    if (e >= NE) return;
    int d = dst[e];
    int pos = atomicAdd(&g_off[d], 1) + g_bsum[d >> 9];
    g_edge[pos] = make_int2(src[e], d);
}

// ---------- node MLPs ----------
__global__ __launch_bounds__(128)
void node_mlp6(const float* __restrict__ x, const float* __restrict__ W,
               const float* __restrict__ b) {
    __shared__ float sWd[6 * 64];
    __shared__ float sWq[6 * 64];
    int tid = threadIdx.x;
    for (int i = tid; i < 6 * 64; i += 128) {
        float wb = W[6 * 64 + i];
        sWd[i] = W[i] - wb;
        sWq[i] = wb;
    }
    __syncthreads();
    int n = blockIdx.x * 128 + tid;
    if (n >= NN) return;
    float xr[6];
#pragma unroll
    for (int j = 0; j < 6; j++) xr[j] = x[(size_t)n * 6 + j];
    float* Pp = g_P + (size_t)n * 64;
    float* Qp = g_Q + (size_t)n * 64;
#pragma unroll 4
    for (int k = 0; k < 64; k++) {
        float p = __ldg(b + k), q = 0.f;
#pragma unroll
        for (int j = 0; j < 6; j++) {
            p = fmaf(xr[j], sWd[j * 64 + k], p);
            q = fmaf(xr[j], sWq[j * 64 + k], q);
        }
        Pp[k] = p;
        Qp[k] = q;
    }
}

// Conv2 node GEMM on tensor cores, cooperative A gather (unchanged from R15).
__global__ __launch_bounds__(128)
void node_mlp64_mma(const float* __restrict__ b3, const float* __restrict__ b2) {
    extern __shared__ char dsm_raw[];
    uint32_t base = smem_u32(dsm_raw);
    uint32_t sAh = base;
    uint32_t sAl = base + 16384;
    uint32_t sBh = base + 32768;
    uint32_t sBl = base + 49152;

    int tid = threadIdx.x;
    int wid = tid >> 5, lane = tid & 31;
    int gq = lane >> 2, tq = lane & 3;

    const uint4* Bh128 = (const uint4*)g_W3h;
    const uint4* Bl128 = (const uint4*)g_W3l;
#pragma unroll
    for (int it = 0; it < 8; it++) {
        int ch = tid + it * 128;
        int n = ch >> 3, jc = ch & 7;
        uint32_t off = (uint32_t)(n * 128) + ((((uint32_t)jc << 4)) ^ ((uint32_t)(n & 7) << 4));
        uint4 vh = Bh128[ch], vl = Bl128[ch];
        sts_v4(sBh + off, vh.x, vh.y, vh.z, vh.w);
        sts_v4(sBl + off, vl.x, vl.y, vl.z, vl.w);
    }

    {
        int part = lane & 15, half = lane >> 4;
        int tilebase = blockIdx.x * 128;
        float4 bb = __ldg(((const float4*)b2) + part);
#pragma unroll
        for (int i = 0; i < 16; i++) {
            int lr = (wid << 5) + 2 * i + half;
            int node = tilebase + lr;
            int cn = node < NN ? node : NN - 1;
            float4 v = ((const float4*)(g_h1 + (size_t)cn * 64))[part];
            float t0 = (__float_as_int(v.x) == (int)NEG_BITS) ? 0.f : lrelu(v.x + bb.x);
            float t1 = (__float_as_int(v.y) == (int)NEG_BITS) ? 0.f : lrelu(v.y + bb.y);
            float t2 = (__float_as_int(v.z) == (int)NEG_BITS) ? 0.f : lrelu(v.z + bb.z);
            float t3 = (__float_as_int(v.w) == (int)NEG_BITS) ? 0.f : lrelu(v.w + bb.w);
            uint32_t h0, h1, l0, l1;
            split4(t0, t1, t2, t3, h0, h1, l0, l1);
            uint32_t addr = (uint32_t)(lr * 128) + (((uint32_t)(part * 8)) ^ ((uint32_t)(lr & 7) << 4));
            sts_v2(sAh + addr, h0, h1);
            sts_v2(sAl + addr, l0, l1);
        }
    }
    __syncthreads();

    float acc[2][16][4];
#pragma unroll
    for (int nt = 0; nt < 16; nt++) {
        int col = nt * 8 + tq * 2;
        float b0 = 0.f, b1 = 0.f;
        if (col < 64) { b0 = __ldg(b3 + col); b1 = __ldg(b3 + col + 1); }
#pragma unroll
        for (int mt = 0; mt < 2; mt++) {
            acc[mt][nt][0] = b0; acc[mt][nt][1] = b1;
            acc[mt][nt][2] = b0; acc[mt][nt][3] = b1;
        }
    }

#pragma unroll
    for (int kt = 0; kt < 4; kt++) {
        uint32_t cb = (uint32_t)(kt * 32 + tq * 4);
        uint32_t ah[2][4], al[2][4];
#pragma unroll
        for (int mt = 0; mt < 2; mt++) {
            int r0 = wid * 32 + mt * 16 + gq;
            uint32_t xr = (uint32_t)(r0 & 7) << 4;
            uint32_t c0 = cb ^ xr, c1 = (cb + 16) ^ xr;
            uint32_t b0 = (uint32_t)(r0 * 128), b1 = b0 + 1024;
            ah[mt][0] = lds32(sAh + b0 + c0); ah[mt][1] = lds32(sAh + b1 + c0);
            ah[mt][2] = lds32(sAh + b0 + c1); ah[mt][3] = lds32(sAh + b1 + c1);
            al[mt][0] = lds32(sAl + b0 + c0); al[mt][1] = lds32(sAl + b1 + c0);
            al[mt][2] = lds32(sAl + b0 + c1); al[mt][3] = lds32(sAl + b1 + c1);
        }
        uint32_t xb = (uint32_t)gq << 4;
        uint32_t cb0 = cb ^ xb, cb1 = (cb + 16) ^ xb;
#pragma unroll
        for (int nt = 0; nt < 16; nt++) {
            uint32_t rb = (uint32_t)((nt * 8 + gq) * 128);
            uint32_t bh0 = lds32(sBh + rb + cb0), bh1 = lds32(sBh + rb + cb1);
            uint32_t bl0 = lds32(sBl + rb + cb0), bl1 = lds32(sBl + rb + cb1);
#pragma unroll
            for (int mt = 0; mt < 2; mt++) {
                mma16816(acc[mt][nt], ah[mt], bh0, bh1);
                mma16816(acc[mt][nt], ah[mt], bl0, bl1);
                mma16816(acc[mt][nt], al[mt], bh0, bh1);
            }
        }
    }

    int tilebase = blockIdx.x * 128;
#pragma unroll
    for (int mt = 0; mt < 2; mt++) {
        int r0 = wid * 32 + mt * 16 + gq;
        int n0 = tilebase + r0, n1 = n0 + 8;
#pragma unroll
        for (int nt = 0; nt < 16; nt++) {
            int col = nt * 8 + tq * 2;
            float* basep = (col < 64) ? g_P : g_Q;
            int c = col & 63;
            if (n0 < NN)
                *(float2*)(basep + (size_t)n0 * 64 + c) = make_float2(acc[mt][nt][0], acc[mt][nt][1]);
            if (n1 < NN)
                *(float2*)(basep + (size_t)n1 * 64 + c) = make_float2(acc[mt][nt][2], acc[mt][nt][3]);
        }
    }
}

// ---------- persistent barrier-free edge kernel ----------
// Per-warp 8KB region at base + wid*8192: A-hi rows [0,4K), A-lo rows [4K,8K);
// D (32 x 256B = 8KB) overlays the same region after the mainloop's last LDSM.
// B shared read-only at base+64K (hi) / +72K (lo). One __syncthreads total.
template <int PASS>
__global__ __launch_bounds__(256, 2)
void edge_mma_kernel() {
    extern __shared__ char dsm_raw[];
    uint32_t base = smem_u32(dsm_raw);
    uint32_t sBh = base + 65536;
    uint32_t sBl = base + 73728;

    int tid = threadIdx.x;
    int wid = tid >> 5, lane = tid & 31;
    int tq = lane & 3, gq = lane >> 2;
    uint32_t wBase = base + (uint32_t)(wid << 13);     // warp's 8KB region

    // Stage B once (vectorized), then the only block barrier.
    const uint4* Bh128 = (const uint4*)g_WhT[PASS - 1];
    const uint4* Bl128 = (const uint4*)g_WlT[PASS - 1];
#pragma unroll
    for (int it = 0; it < 2; it++) {
        int ch = tid + it * 256;
        int n = ch >> 3, jc = ch & 7;
        uint32_t off = (uint32_t)(n * 128) + ((((uint32_t)jc << 4)) ^ ((uint32_t)(n & 7) << 4));
        uint4 vh = Bh128[ch], vl = Bl128[ch];
        sts_v4(sBh + off, vh.x, vh.y, vh.z, vh.w);
        sts_v4(sBl + off, vl.x, vl.y, vl.z, vl.w);
    }
    __syncthreads();

    // ldmatrix lane geometry (warp-local rows 0..31)
    int l8 = lane & 7, mface = lane >> 3;
    uint32_t colp = (uint32_t)(mface >> 1) * 16;
    int rsel = (mface & 1) * 8 + l8;
    uint32_t aOffH[2], aOffL[2];
#pragma unroll
    for (int mt = 0; mt < 2; mt++) {
        int r = mt * 16 + rsel;                         // local row 0..31
        uint32_t xr = (uint32_t)(r & 7) << 4;
        aOffH[mt] = (uint32_t)(r * 128);
        aOffL[mt] = aOffH[mt] + 4096u;
        aOffH[mt] += 0;
        (void)xr;
    }
    uint32_t aX[2];
#pragma unroll
    for (int mt = 0; mt < 2; mt++) aX[mt] = (uint32_t)((mt * 16 + rsel) & 7) << 4;
    uint32_t bBase[4], bX[4];
#pragma unroll
    for (int p = 0; p < 4; p++) {
        int n = p * 16 + rsel;
        bBase[p] = (uint32_t)(n * 128);
        bX[p] = (uint32_t)(n & 7) << 4;
    }

    int warpsTotal = (int)gridDim.x * 8;
    int wg = blockIdx.x * 8 + wid;
    float* agg = (PASS == 1) ? g_h1 : g_h2;

    for (int chk = wg; chk < NCHUNK; chk += warpsTotal) {
        // Own edge of this chunk
        int2 sd = g_edge[chk * 32 + lane];

        // Cooperative A gather: indices via warp shuffle; 16 lanes per row, 2 rows/iter.
        {
            int part = lane & 15, half = lane >> 4;
#pragma unroll
            for (int i = 0; i < 16; i++) {
                int lk = 2 * i + half;                   // local edge 0..31
                int dd = __shfl_sync(0xffffffffu, sd.y, lk);
                int ss = __shfl_sync(0xffffffffu, sd.x, lk);
                float4 p = ((const float4*)(g_P + (size_t)dd * 64))[part];
                float4 q = ((const float4*)(g_Q + (size_t)ss * 64))[part];
                float t0 = lrelu(p.x + q.x), t1 = lrelu(p.y + q.y);
                float t2 = lrelu(p.z + q.z), t3 = lrelu(p.w + q.w);
                uint32_t h0, h1, l0, l1;
                split4(t0, t1, t2, t3, h0, h1, l0, l1);
                uint32_t cby = ((uint32_t)(part * 8)) ^ ((uint32_t)(lk & 7) << 4);
                uint32_t roff = (uint32_t)(lk * 128) + cby;
                sts_v2(wBase + roff, h0, h1);
                sts_v2(wBase + 4096u + roff, l0, l1);
            }
        }
        __syncwarp();

        // Mainloop (warp-local A, shared B)
        float acc[2][8][4];
#pragma unroll
        for (int mt = 0; mt < 2; mt++)
#pragma unroll
            for (int nt = 0; nt < 8; nt++)
#pragma unroll
                for (int r = 0; r < 4; r++) acc[mt][nt][r] = 0.f;

#pragma unroll
        for (int kt = 0; kt < 4; kt++) {
            uint32_t kb = (uint32_t)(kt * 32) + colp;
            uint32_t ah[2][4], al[2][4];
#pragma unroll
            for (int mt = 0; mt < 2; mt++) {
                uint32_t off = kb ^ aX[mt];
                ldsm_x4(ah[mt], wBase + aOffH[mt] + off);
                ldsm_x4(al[mt], wBase + aOffL[mt] + off);
            }
#pragma unroll
            for (int p = 0; p < 4; p++) {
                uint32_t off = kb ^ bX[p];
                uint32_t bh[4], bl[4];
                ldsm_x4(bh, sBh + bBase[p] + off);
                ldsm_x4(bl, sBl + bBase[p] + off);
#pragma unroll
                for (int mt = 0; mt < 2; mt++) {
                    mma16816(acc[mt][2 * p],     ah[mt], bh[0], bh[2]);
                    mma16816(acc[mt][2 * p],     ah[mt], bl[0], bl[2]);
                    mma16816(acc[mt][2 * p],     al[mt], bh[0], bh[2]);
                    mma16816(acc[mt][2 * p + 1], ah[mt], bh[1], bh[3]);
                    mma16816(acc[mt][2 * p + 1], ah[mt], bl[1], bl[3]);
                    mma16816(acc[mt][2 * p + 1], al[mt], bh[1], bh[3]);
                }
            }
        }
        __syncwarp();

        // D store overlaying warp's A region: local row k at wBase + k*256, 32B-granule swizzle.
#pragma unroll
        for (int mt = 0; mt < 2; mt++) {
            int r0 = mt * 16 + gq;                       // local rows r0, r0+8
            uint32_t xd = (uint32_t)(r0 & 7) << 5;
            uint32_t rb0 = (uint32_t)(r0 * 256), rb1 = rb0 + 2048;
#pragma unroll
            for (int nt = 0; nt < 8; nt++) {
                uint32_t cby = (uint32_t)((nt * 8 + tq * 2) * 4) ^ xd;
                sts_v2f(wBase + rb0 + cby, acc[mt][nt][0], acc[mt][nt][1]);
                sts_v2f(wBase + rb1 + cby, acc[mt][nt][2], acc[mt][nt][3]);
            }
        }
        __syncwarp();

        // Epilogue: thread owns channel pair (2*lane, 2*lane+1) over the warp's 32 edges.
        uint32_t cb2 = (uint32_t)lane * 8;
        int curd = __shfl_sync(0xffffffffu, sd.y, 0);
        float2 mx = make_float2(-3.0e38f, -3.0e38f);
#pragma unroll
        for (int b = 0; b < 4; b++) {
            int dd[8];
            float2 v[8];
#pragma unroll
            for (int j = 0; j < 8; j++) {
                int k = b * 8 + j;
                dd[j] = __shfl_sync(0xffffffffu, sd.y, k);
                v[j] = lds_v2f(wBase + (uint32_t)(k * 256) + (cb2 ^ ((uint32_t)(k & 7) << 5)));
            }
#pragma unroll
            for (int j = 0; j < 8; j++) {
                if (dd[j] != curd) {
                    atomMaxF(agg + (size_t)curd * 64 + 2 * lane, mx.x);
                    atomMaxF(agg + (size_t)curd * 64 + 2 * lane + 1, mx.y);
                    curd = dd[j];
                    mx = v[j];
                } else {
                    mx.x = fmaxf(mx.x, v[j].x);
                    mx.y = fmaxf(mx.y, v[j].y);
                }
            }
        }
        atomMaxF(agg + (size_t)curd * 64 + 2 * lane, mx.x);
        atomMaxF(agg + (size_t)curd * 64 + 2 * lane + 1, mx.y);
        __syncwarp();
    }
}

// ---------- pooling / classifier ----------
__global__ void pool_kernel(const int* __restrict__ batch, const float* __restrict__ bprev) {
    int g = blockIdx.x, q = blockIdx.y;
    int lo = 0, hi = NN;
    while (lo < hi) { int m = (lo + hi) >> 1; if (batch[m] < g) lo = m + 1; else hi = m; }
    int start = lo;
    hi = NN;
    while (lo < hi) { int m = (lo + hi) >> 1; if (batch[m] <= g) lo = m + 1; else hi = m; }
    int end = lo;
    int len = end - start;
    int qs = start + (len * q) / 4;
    int qe = start + (len * (q + 1)) / 4;

    int tid = threadIdx.x;
    int k = tid & 63, grp = tid >> 6;
    float bk = __ldg(bprev + k);
    float s = 0.f;
    float mx = -3.0e38f;
    for (int n = qs + grp; n < qe; n += 4) {
        float z = g_h2[(size_t)n * H + k];
        float v = (__float_as_int(z) == (int)NEG_BITS) ? 0.f : lrelu(z + bk);
        s += v;
        mx = fmaxf(mx, v);
    }
    __shared__ float ss[256], sm[256];
    ss[tid] = s; sm[tid] = mx;
    __syncthreads();
    if (grp == 0) {
        s += ss[64 + k] + ss[128 + k] + ss[192 + k];
        mx = fmaxf(fmaxf(mx, sm[64 + k]), fmaxf(sm[128 + k], sm[192 + k]));
        g_psum[(g * 4 + q) * 64 + k] = s;
        g_pmax[(g * 4 + q) * 64 + k] = mx;
    }
    if (q == 0 && tid == 0) g_pcnt[g] = len;
}

__global__ void cls_kernel(const float* __restrict__ Wc1, const float* __restrict__ bc1,
                           const float* __restrict__ Wc2, const float* __restrict__ bc2,
                           float* __restrict__ out) {
    int g = blockIdx.x, t = threadIdx.x;
    __shared__ float gv[128];
    int cnt = g_pcnt[g];
    {
        float s = g_psum[(g * 4 + 0) * 64 + t] + g_psum[(g * 4 + 1) * 64 + t]
                + g_psum[(g * 4 + 2) * 64 + t] + g_psum[(g * 4 + 3) * 64 + t];
        float m = fmaxf(fmaxf(g_pmax[(g * 4 + 0) * 64 + t], g_pmax[(g * 4 + 1) * 64 + t]),
                        fmaxf(g_pmax[(g * 4 + 2) * 64 + t], g_pmax[(g * 4 + 3) * 64 + t]));
        gv[t] = s / (float)(cnt > 1 ? cnt : 1);
        gv[t + 64] = (cnt > 0) ? m : 0.f;
    }
    __syncthreads();
    float acc = __ldg(bc1 + t);
#pragma unroll 8
    for (int j = 0; j < 128; j++) acc = fmaf(gv[j], Wc1[j * 64 + t], acc);
    float v = lrelu(acc) * __ldg(Wc2 + t);
#pragma unroll
    for (int o = 16; o > 0; o >>= 1) v += __shfl_down_sync(0xffffffffu, v, o);
    __shared__ float part[2];
    if ((t & 31) == 0) part[t >> 5] = v;
    __syncthreads();
    if (t == 0) out[g] = part[0] + part[1] + __ldg(bc2);
}

extern "C" void kernel_launch(void* const* d_in, const int* in_sizes, int n_in,
                              void* d_out, int out_size) {
    const float* x    = (const float*)d_in[0];
    const int*   ei   = (const int*)d_in[1];
    const int*   batch= (const int*)d_in[2];
    const float* W1   = (const float*)d_in[3];
    const float* b1   = (const float*)d_in[4];
    const float* W2   = (const float*)d_in[5];
    const float* b2   = (const float*)d_in[6];
    const float* W3   = (const float*)d_in[7];
    const float* b3   = (const float*)d_in[8];
    const float* W4   = (const float*)d_in[9];
    const float* b4   = (const float*)d_in[10];
    const float* Wc1  = (const float*)d_in[11];
    const float* bc1  = (const float*)d_in[12];
    const float* Wc2  = (const float*)d_in[13];
    const float* bc2  = (const float*)d_in[14];
    float* out = (float*)d_out;

    const int* src = ei;
    const int* dst = ei + NE;

    const int DSM_E = 81920;   // A/D 64K + B 16K
    const int DSM_N = 65536;
    cudaFuncSetAttribute(edge_mma_kernel<1>, cudaFuncAttributeMaxDynamicSharedMemorySize, DSM_E);
    cudaFuncSetAttribute(edge_mma_kernel<2>, cudaFuncAttributeMaxDynamicSharedMemorySize, DSM_E);
    cudaFuncSetAttribute(node_mlp64_mma, cudaFuncAttributeMaxDynamicSharedMemorySize, DSM_N);

    const int NB = (NN + 511) / 512;   // 98
    setup_kernel<<<3189, 256>>>(W2, W4, W3);
    hist_kernel<<<(NE + 255) / 256, 256>>>(dst);
    bscan_kernel<<<NB, 512>>>();
    topscan_kernel<<<1, 128>>>(NB);
    scatter_kernel<<<(NE + 255) / 256, 256>>>(src, dst);
    node_mlp6<<<(NN + 127) / 128, 128>>>(x, W1, b1);
    edge_mma_kernel<1><<<NCTA_E, 256, DSM_E>>>();
    node_mlp64_mma<<<(NN + 127) / 128, 128, DSM_N>>>(b3, b2);
    edge_mma_kernel<2><<<NCTA_E, 256, DSM_E>>>();
    pool_kernel<<<dim3(NG, 4), 256>>>(batch, b4);
    cls_kernel<<<NG, 64>>>(Wc1, bc1, Wc2, bc2, out);
}

// round 17
// speedup vs baseline: 1.2274x; 1.0046x over previous
#include <cuda_runtime.h>
#include <cuda_bf16.h>
#include <cstdint>

#define NN 50000
#define NE 1280000
#define NG 64
#define H  64
#define NEG_BITS 0xFF800000u
#define NCHUNK (NE / 16)       // 80000 16-edge chunks
#define NCTA_E 456             // persistent CTAs (3 per SM)

// Scratch (device globals; allocation forbidden)
__device__ float g_h1[NN * H];
__device__ float g_h2[NN * H];
__device__ float g_P[NN * H];
__device__ float g_Q[NN * H];
__device__ int   g_cnt[NN + 1];
__device__ int   g_off[NN + 1];
__device__ int   g_bsum[128];
__device__ int2  g_edge[NE];
__device__ __nv_bfloat16 g_WhT[2][4096];
__device__ __nv_bfloat16 g_WlT[2][4096];
__device__ __nv_bfloat16 g_W3h[8192];
__device__ __nv_bfloat16 g_W3l[8192];
__device__ float g_psum[NG * 4 * 64];
__device__ float g_pmax[NG * 4 * 64];
__device__ int   g_pcnt[NG];

__device__ __forceinline__ float lrelu(float x) { return fmaxf(x, 0.2f * x); }

__device__ __forceinline__ void atomMaxF(float* a, float v) {
    int bi = __float_as_int(v);
    if (bi == (int)0x80000000) bi = 0;
    if (bi >= 0) atomicMax((int*)a, bi);
    else         atomicMin((unsigned int*)a, (unsigned int)bi);
}

__device__ __forceinline__ uint32_t smem_u32(const void* p) {
    uint32_t a;
    asm("{ .reg .u64 t; cvta.to.shared.u64 t, %1; cvt.u32.u64 %0, t; }" : "=r"(a) : "l"(p));
    return a;
}
__device__ __forceinline__ uint32_t lds32(uint32_t a) {
    uint32_t v;
    asm volatile("ld.shared.b32 %0, [%1];" : "=r"(v) : "r"(a));
    return v;
}
__device__ __forceinline__ void sts_v2(uint32_t a, uint32_t x, uint32_t y) {
    asm volatile("st.shared.v2.b32 [%0], {%1,%2};" :: "r"(a), "r"(x), "r"(y) : "memory");
}
__device__ __forceinline__ void sts_v4(uint32_t a, uint32_t x, uint32_t y, uint32_t z, uint32_t w) {
    asm volatile("st.shared.v4.b32 [%0], {%1,%2,%3,%4};" :: "r"(a), "r"(x), "r"(y), "r"(z), "r"(w) : "memory");
}
__device__ __forceinline__ void sts_v2f(uint32_t a, float x, float y) {
    asm volatile("st.shared.v2.f32 [%0], {%1,%2};" :: "r"(a), "f"(x), "f"(y) : "memory");
}
__device__ __forceinline__ float2 lds_v2f(uint32_t a) {
    float2 v;
    asm volatile("ld.shared.v2.f32 {%0,%1}, [%2];" : "=f"(v.x), "=f"(v.y) : "r"(a));
    return v;
}
__device__ __forceinline__ uint32_t cvt2bf(float hi, float lo) {
    uint32_t r;
    asm("cvt.rn.bf16x2.f32 %0, %1, %2;" : "=r"(r) : "f"(hi), "f"(lo));
    return r;
}
__device__ __forceinline__ void ldsm_x4(uint32_t r[4], uint32_t addr) {
    asm volatile("ldmatrix.sync.aligned.m8n8.x4.shared.b16 {%0,%1,%2,%3}, [%4];"
        : "=r"(r[0]), "=r"(r[1]), "=r"(r[2]), "=r"(r[3]) : "r"(addr));
}

__device__ __forceinline__ void mma16816(float c[4], const uint32_t a[4], uint32_t b0, uint32_t b1) {
    asm volatile(
        "mma.sync.aligned.m16n8k16.row.col.f32.bf16.bf16.f32 "
        "{%0,%1,%2,%3}, {%4,%5,%6,%7}, {%8,%9}, {%0,%1,%2,%3};"
        : "+f"(c[0]), "+f"(c[1]), "+f"(c[2]), "+f"(c[3])
        : "r"(a[0]), "r"(a[1]), "r"(a[2]), "r"(a[3]), "r"(b0), "r"(b1));
}

__device__ __forceinline__ void split4(float t0, float t1, float t2, float t3,
                                       uint32_t& h0, uint32_t& h1, uint32_t& l0, uint32_t& l1) {
    h0 = cvt2bf(t1, t0);
    h1 = cvt2bf(t3, t2);
    l0 = cvt2bf(t1 - __uint_as_float(h0 & 0xFFFF0000u), t0 - __uint_as_float(h0 << 16));
    l1 = cvt2bf(t3 - __uint_as_float(h1 & 0xFFFF0000u), t2 - __uint_as_float(h1 << 16));
}

// ---------- fused setup ----------
__global__ void setup_kernel(const float* __restrict__ W2, const float* __restrict__ W4,
                             const float* __restrict__ W3) {
    int blk = blockIdx.x;
    if (blk < 3125) {
        int i = blk * 256 + threadIdx.x;
        float ni = __int_as_float((int)NEG_BITS);
        float4 v = make_float4(ni, ni, ni, ni);
        if (i < NN * H / 4) {
            ((float4*)g_h1)[i] = v;
            ((float4*)g_h2)[i] = v;
        }
        if (i <= NN) g_cnt[i] = 0;
    } else if (blk < 3157) {
        int i = (blk - 3125) * 256 + threadIdx.x;
        int c = i >> 12, idx = i & 4095;
        const float* W = c ? W4 : W2;
        int n = idx >> 6, j = idx & 63;
        float w = W[j * 64 + n];
        __nv_bfloat16 h = __float2bfloat16_rn(w);
        g_WhT[c][idx] = h;
        g_WlT[c][idx] = __float2bfloat16_rn(w - __bfloat162float(h));
    } else {
        int i = (blk - 3157) * 256 + threadIdx.x;
        int n = i >> 6, j = i & 63;
        float w;
        if (n < 64) w = W3[j * 64 + n] - W3[(64 + j) * 64 + n];
        else        w = W3[(64 + j) * 64 + (n - 64)];
        __nv_bfloat16 h = __float2bfloat16_rn(w);
        g_W3h[i] = h;
        g_W3l[i] = __float2bfloat16_rn(w - __bfloat162float(h));
    }
}

__global__ void hist_kernel(const int* __restrict__ dst) {
    int e = blockIdx.x * blockDim.x + threadIdx.x;
    if (e < NE) atomicAdd(&g_cnt[dst[e]], 1);
}

__global__ void bscan_kernel() {
    int tid = threadIdx.x;
    int i = blockIdx.x * 512 + tid;
    int v = (i < NN) ? g_cnt[i] : 0;
    int lane = tid & 31, wid = tid >> 5;
    int x = v;
#pragma unroll
    for (int o = 1; o < 32; o <<= 1) {
        int y = __shfl_up_sync(0xffffffffu, x, o);
        if (lane >= o) x += y;
    }
    __shared__ int ws[16];
    if (lane == 31) ws[wid] = x;
    __syncthreads();
    if (wid == 0 && lane < 16) {
        int y = ws[lane];
#pragma unroll
        for (int o = 1; o < 16; o <<= 1) {
            int z = __shfl_up_sync(0xffffu, y, o);
            if (lane >= o) y += z;
        }
        ws[lane] = y;
    }
    __syncthreads();
    int base = wid ? ws[wid - 1] : 0;
    if (i < NN) g_off[i] = base + x - v;
    if (tid == 511) g_bsum[blockIdx.x] = base + x;
}

__global__ void topscan_kernel(int nb) {
    __shared__ int s[128];
    int t = threadIdx.x;
    s[t] = (t < nb) ? g_bsum[t] : 0;
    __syncthreads();
    for (int o = 1; o < 128; o <<= 1) {
        int v = (t >= o) ? s[t - o] : 0;
        __syncthreads();
        s[t] += v;
        __syncthreads();
    }
    if (t < nb) g_bsum[t] = (t == 0) ? 0 : s[t - 1];
}

__global__ void scatter_kernel(const int* __restrict__ src, const int* __restrict__ dst) {
    int e = blockIdx.x * blockDim.x + threadIdx.x;
    if (e >= NE) return;
    int d = dst[e];
    int pos = atomicAdd(&g_off[d], 1) + g_bsum[d >> 9];
    g_edge[pos] = make_int2(src[e], d);
}

// ---------- node MLPs ----------
__global__ __launch_bounds__(128)
void node_mlp6(const float* __restrict__ x, const float* __restrict__ W,
               const float* __restrict__ b) {
    __shared__ float sWd[6 * 64];
    __shared__ float sWq[6 * 64];
    int tid = threadIdx.x;
    for (int i = tid; i < 6 * 64; i += 128) {
        float wb = W[6 * 64 + i];
        sWd[i] = W[i] - wb;
        sWq[i] = wb;
    }
    __syncthreads();
    int n = blockIdx.x * 128 + tid;
    if (n >= NN) return;
    float xr[6];
#pragma unroll
    for (int j = 0; j < 6; j++) xr[j] = x[(size_t)n * 6 + j];
    float* Pp = g_P + (size_t)n * 64;
    float* Qp = g_Q + (size_t)n * 64;
#pragma unroll 4
    for (int k = 0; k < 64; k++) {
        float p = __ldg(b + k), q = 0.f;
#pragma unroll
        for (int j = 0; j < 6; j++) {
            p = fmaf(xr[j], sWd[j * 64 + k], p);
            q = fmaf(xr[j], sWq[j * 64 + k], q);
        }
        Pp[k] = p;
        Qp[k] = q;
    }
}

// Conv2 node GEMM on tensor cores, cooperative A gather (unchanged).
__global__ __launch_bounds__(128)
void node_mlp64_mma(const float* __restrict__ b3, const float* __restrict__ b2) {
    extern __shared__ char dsm_raw[];
    uint32_t base = smem_u32(dsm_raw);
    uint32_t sAh = base;
    uint32_t sAl = base + 16384;
    uint32_t sBh = base + 32768;
    uint32_t sBl = base + 49152;

    int tid = threadIdx.x;
    int wid = tid >> 5, lane = tid & 31;
    int gq = lane >> 2, tq = lane & 3;

    const uint4* Bh128 = (const uint4*)g_W3h;
    const uint4* Bl128 = (const uint4*)g_W3l;
#pragma unroll
    for (int it = 0; it < 8; it++) {
        int ch = tid + it * 128;
        int n = ch >> 3, jc = ch & 7;
        uint32_t off = (uint32_t)(n * 128) + ((((uint32_t)jc << 4)) ^ ((uint32_t)(n & 7) << 4));
        uint4 vh = Bh128[ch], vl = Bl128[ch];
        sts_v4(sBh + off, vh.x, vh.y, vh.z, vh.w);
        sts_v4(sBl + off, vl.x, vl.y, vl.z, vl.w);
    }

    {
        int part = lane & 15, half = lane >> 4;
        int tilebase = blockIdx.x * 128;
        float4 bb = __ldg(((const float4*)b2) + part);
#pragma unroll
        for (int i = 0; i < 16; i++) {
            int lr = (wid << 5) + 2 * i + half;
            int node = tilebase + lr;
            int cn = node < NN ? node : NN - 1;
            float4 v = ((const float4*)(g_h1 + (size_t)cn * 64))[part];
            float t0 = (__float_as_int(v.x) == (int)NEG_BITS) ? 0.f : lrelu(v.x + bb.x);
            float t1 = (__float_as_int(v.y) == (int)NEG_BITS) ? 0.f : lrelu(v.y + bb.y);
            float t2 = (__float_as_int(v.z) == (int)NEG_BITS) ? 0.f : lrelu(v.z + bb.z);
            float t3 = (__float_as_int(v.w) == (int)NEG_BITS) ? 0.f : lrelu(v.w + bb.w);
            uint32_t h0, h1, l0, l1;
            split4(t0, t1, t2, t3, h0, h1, l0, l1);
            uint32_t addr = (uint32_t)(lr * 128) + (((uint32_t)(part * 8)) ^ ((uint32_t)(lr & 7) << 4));
            sts_v2(sAh + addr, h0, h1);
            sts_v2(sAl + addr, l0, l1);
        }
    }
    __syncthreads();

    float acc[2][16][4];
#pragma unroll
    for (int nt = 0; nt < 16; nt++) {
        int col = nt * 8 + tq * 2;
        float b0 = 0.f, b1 = 0.f;
        if (col < 64) { b0 = __ldg(b3 + col); b1 = __ldg(b3 + col + 1); }
#pragma unroll
        for (int mt = 0; mt < 2; mt++) {
            acc[mt][nt][0] = b0; acc[mt][nt][1] = b1;
            acc[mt][nt][2] = b0; acc[mt][nt][3] = b1;
        }
    }

#pragma unroll
    for (int kt = 0; kt < 4; kt++) {
        uint32_t cb = (uint32_t)(kt * 32 + tq * 4);
        uint32_t ah[2][4], al[2][4];
#pragma unroll
        for (int mt = 0; mt < 2; mt++) {
            int r0 = wid * 32 + mt * 16 + gq;
            uint32_t xr = (uint32_t)(r0 & 7) << 4;
            uint32_t c0 = cb ^ xr, c1 = (cb + 16) ^ xr;
            uint32_t b0 = (uint32_t)(r0 * 128), b1 = b0 + 1024;
            ah[mt][0] = lds32(sAh + b0 + c0); ah[mt][1] = lds32(sAh + b1 + c0);
            ah[mt][2] = lds32(sAh + b0 + c1); ah[mt][3] = lds32(sAh + b1 + c1);
            al[mt][0] = lds32(sAl + b0 + c0); al[mt][1] = lds32(sAl + b1 + c0);
            al[mt][2] = lds32(sAl + b0 + c1); al[mt][3] = lds32(sAl + b1 + c1);
        }
        uint32_t xb = (uint32_t)gq << 4;
        uint32_t cb0 = cb ^ xb, cb1 = (cb + 16) ^ xb;
#pragma unroll
        for (int nt = 0; nt < 16; nt++) {
            uint32_t rb = (uint32_t)((nt * 8 + gq) * 128);
            uint32_t bh0 = lds32(sBh + rb + cb0), bh1 = lds32(sBh + rb + cb1);
            uint32_t bl0 = lds32(sBl + rb + cb0), bl1 = lds32(sBl + rb + cb1);
#pragma unroll
            for (int mt = 0; mt < 2; mt++) {
                mma16816(acc[mt][nt], ah[mt], bh0, bh1);
                mma16816(acc[mt][nt], ah[mt], bl0, bl1);
                mma16816(acc[mt][nt], al[mt], bh0, bh1);
            }
        }
    }

    int tilebase = blockIdx.x * 128;
#pragma unroll
    for (int mt = 0; mt < 2; mt++) {
        int r0 = wid * 32 + mt * 16 + gq;
        int n0 = tilebase + r0, n1 = n0 + 8;
#pragma unroll
        for (int nt = 0; nt < 16; nt++) {
            int col = nt * 8 + tq * 2;
            float* basep = (col < 64) ? g_P : g_Q;
            int c = col & 63;
            if (n0 < NN)
                *(float2*)(basep + (size_t)n0 * 64 + c) = make_float2(acc[mt][nt][0], acc[mt][nt][1]);
            if (n1 < NN)
                *(float2*)(basep + (size_t)n1 * 64 + c) = make_float2(acc[mt][nt][2], acc[mt][nt][3]);
        }
    }
}

// ---------- persistent edge kernel: 16-edge warp chunks, 3 CTAs/SM ----------
// Per-warp 4KB region at base + wid*4096: A-hi rows [0,2K), A-lo [2K,4K);
// D (16 x 256B = 4KB) overlays after mainloop. B shared at base+32K(hi)/+40K(lo).
template <int PASS>
__global__ __launch_bounds__(256, 3)
void edge_mma_kernel() {
    extern __shared__ char dsm_raw[];
    uint32_t base = smem_u32(dsm_raw);
    uint32_t sBh = base + 32768;
    uint32_t sBl = base + 40960;

    int tid = threadIdx.x;
    int wid = tid >> 5, lane = tid & 31;
    int tq = lane & 3, gq = lane >> 2;
    uint32_t wBase = base + (uint32_t)(wid << 12);     // warp's 4KB region

    // Stage B once, then the only block barrier.
    const uint4* Bh128 = (const uint4*)g_WhT[PASS - 1];
    const uint4* Bl128 = (const uint4*)g_WlT[PASS - 1];
#pragma unroll
    for (int it = 0; it < 2; it++) {
        int ch = tid + it * 256;
        int n = ch >> 3, jc = ch & 7;
        uint32_t off = (uint32_t)(n * 128) + ((((uint32_t)jc << 4)) ^ ((uint32_t)(n & 7) << 4));
        uint4 vh = Bh128[ch], vl = Bl128[ch];
        sts_v4(sBh + off, vh.x, vh.y, vh.z, vh.w);
        sts_v4(sBl + off, vl.x, vl.y, vl.z, vl.w);
    }
    __syncthreads();

    // ldmatrix lane geometry (warp-local rows 0..15)
    int l8 = lane & 7, mface = lane >> 3;
    uint32_t colp = (uint32_t)(mface >> 1) * 16;
    int rsel = (mface & 1) * 8 + l8;                   // 0..15
    uint32_t aOff = (uint32_t)(rsel * 128);
    uint32_t aX = (uint32_t)(rsel & 7) << 4;
    uint32_t bBase[4], bX[4];
#pragma unroll
    for (int p = 0; p < 4; p++) {
        int n = p * 16 + rsel;
        bBase[p] = (uint32_t)(n * 128);
        bX[p] = (uint32_t)(n & 7) << 4;
    }

    int warpsTotal = (int)gridDim.x * 8;
    int wg = blockIdx.x * 8 + wid;
    float* agg = (PASS == 1) ? g_h1 : g_h2;

    for (int chk = wg; chk < NCHUNK; chk += warpsTotal) {
        // Own edge of this chunk (lanes 16-31 mirror lanes 0-15)
        int2 sd = g_edge[chk * 16 + (lane & 15)];

        // Cooperative A gather: 16 lanes per 256B row, 2 edges/iter, 8 iters.
        {
            int part = lane & 15, half = lane >> 4;
#pragma unroll
            for (int i = 0; i < 8; i++) {
                int lk = 2 * i + half;                   // local edge 0..15
                int dd = __shfl_sync(0xffffffffu, sd.y, lk);
                int ss = __shfl_sync(0xffffffffu, sd.x, lk);
                float4 p = ((const float4*)(g_P + (size_t)dd * 64))[part];
                float4 q = ((const float4*)(g_Q + (size_t)ss * 64))[part];
                float t0 = lrelu(p.x + q.x), t1 = lrelu(p.y + q.y);
                float t2 = lrelu(p.z + q.z), t3 = lrelu(p.w + q.w);
                uint32_t h0, h1, l0, l1;
                split4(t0, t1, t2, t3, h0, h1, l0, l1);
                uint32_t cby = ((uint32_t)(part * 8)) ^ ((uint32_t)(lk & 7) << 4);
                uint32_t roff = (uint32_t)(lk * 128) + cby;
                sts_v2(wBase + roff, h0, h1);
                sts_v2(wBase + 2048u + roff, l0, l1);
            }
        }
        __syncwarp();

        // Mainloop (warp-local A, shared B); M=16 per chunk.
        float acc[8][4];
#pragma unroll
        for (int nt = 0; nt < 8; nt++)
#pragma unroll
            for (int r = 0; r < 4; r++) acc[nt][r] = 0.f;

#pragma unroll
        for (int kt = 0; kt < 4; kt++) {
            uint32_t kb = (uint32_t)(kt * 32) + colp;
            uint32_t ah[4], al[4];
            uint32_t offA = kb ^ aX;
            ldsm_x4(ah, wBase + aOff + offA);
            ldsm_x4(al, wBase + 2048u + aOff + offA);
#pragma unroll
            for (int p = 0; p < 4; p++) {
                uint32_t off = kb ^ bX[p];
                uint32_t bh[4], bl[4];
                ldsm_x4(bh, sBh + bBase[p] + off);
                ldsm_x4(bl, sBl + bBase[p] + off);
                mma16816(acc[2 * p],     ah, bh[0], bh[2]);
                mma16816(acc[2 * p],     ah, bl[0], bl[2]);
                mma16816(acc[2 * p],     al, bh[0], bh[2]);
                mma16816(acc[2 * p + 1], ah, bh[1], bh[3]);
                mma16816(acc[2 * p + 1], ah, bl[1], bl[3]);
                mma16816(acc[2 * p + 1], al, bh[1], bh[3]);
            }
        }
        __syncwarp();

        // D store overlaying warp's 4KB region: local row k at wBase + k*256, 32B swizzle.
        {
            int r0 = gq;                                 // rows gq, gq+8
            uint32_t xd = (uint32_t)(r0 & 7) << 5;
            uint32_t rb0 = (uint32_t)(r0 * 256), rb1 = rb0 + 2048;
#pragma unroll
            for (int nt = 0; nt < 8; nt++) {
                uint32_t cby = (uint32_t)((nt * 8 + tq * 2) * 4) ^ xd;
                sts_v2f(wBase + rb0 + cby, acc[nt][0], acc[nt][1]);
                sts_v2f(wBase + rb1 + cby, acc[nt][2], acc[nt][3]);
            }
        }
        __syncwarp();

        // Epilogue: thread owns channel pair (2*lane, 2*lane+1) over the 16 edges.
        uint32_t cb2 = (uint32_t)lane * 8;
        int curd = __shfl_sync(0xffffffffu, sd.y, 0);
        float2 mx = make_float2(-3.0e38f, -3.0e38f);
#pragma unroll
        for (int b = 0; b < 2; b++) {
            int dd[8];
            float2 v[8];
#pragma unroll
            for (int j = 0; j < 8; j++) {
                int k = b * 8 + j;
                dd[j] = __shfl_sync(0xffffffffu, sd.y, k);
                v[j] = lds_v2f(wBase + (uint32_t)(k * 256) + (cb2 ^ ((uint32_t)(k & 7) << 5)));
            }
#pragma unroll
            for (int j = 0; j < 8; j++) {
                if (dd[j] != curd) {
                    atomMaxF(agg + (size_t)curd * 64 + 2 * lane, mx.x);
                    atomMaxF(agg + (size_t)curd * 64 + 2 * lane + 1, mx.y);
                    curd = dd[j];
                    mx = v[j];
                } else {
                    mx.x = fmaxf(mx.x, v[j].x);
                    mx.y = fmaxf(mx.y, v[j].y);
                }
            }
        }
        atomMaxF(agg + (size_t)curd * 64 + 2 * lane, mx.x);
        atomMaxF(agg + (size_t)curd * 64 + 2 * lane + 1, mx.y);
        __syncwarp();
    }
}

// ---------- pooling / classifier ----------
__global__ void pool_kernel(const int* __restrict__ batch, const float* __restrict__ bprev) {
    int g = blockIdx.x, q = blockIdx.y;
    int lo = 0, hi = NN;
    while (lo < hi) { int m = (lo + hi) >> 1; if (batch[m] < g) lo = m + 1; else hi = m; }
    int start = lo;
    hi = NN;
    while (lo < hi) { int m = (lo + hi) >> 1; if (batch[m] <= g) lo = m + 1; else hi = m; }
    int end = lo;
    int len = end - start;
    int qs = start + (len * q) / 4;
    int qe = start + (len * (q + 1)) / 4;

    int tid = threadIdx.x;
    int k = tid & 63, grp = tid >> 6;
    float bk = __ldg(bprev + k);
    float s = 0.f;
    float mx = -3.0e38f;
    for (int n = qs + grp; n < qe; n += 4) {
        float z = g_h2[(size_t)n * H + k];
        float v = (__float_as_int(z) == (int)NEG_BITS) ? 0.f : lrelu(z + bk);
        s += v;
        mx = fmaxf(mx, v);
    }
    __shared__ float ss[256], sm[256];
    ss[tid] = s; sm[tid] = mx;
    __syncthreads();
    if (grp == 0) {
        s += ss[64 + k] + ss[128 + k] + ss[192 + k];
        mx = fmaxf(fmaxf(mx, sm[64 + k]), fmaxf(sm[128 + k], sm[192 + k]));
        g_psum[(g * 4 + q) * 64 + k] = s;
        g_pmax[(g * 4 + q) * 64 + k] = mx;
    }
    if (q == 0 && tid == 0) g_pcnt[g] = len;
}

__global__ void cls_kernel(const float* __restrict__ Wc1, const float* __restrict__ bc1,
                           const float* __restrict__ Wc2, const float* __restrict__ bc2,
                           float* __restrict__ out) {
    int g = blockIdx.x, t = threadIdx.x;
    __shared__ float gv[128];
    int cnt = g_pcnt[g];
    {
        float s = g_psum[(g * 4 + 0) * 64 + t] + g_psum[(g * 4 + 1) * 64 + t]
                + g_psum[(g * 4 + 2) * 64 + t] + g_psum[(g * 4 + 3) * 64 + t];
        float m = fmaxf(fmaxf(g_pmax[(g * 4 + 0) * 64 + t], g_pmax[(g * 4 + 1) * 64 + t]),
                        fmaxf(g_pmax[(g * 4 + 2) * 64 + t], g_pmax[(g * 4 + 3) * 64 + t]));
        gv[t] = s / (float)(cnt > 1 ? cnt : 1);
        gv[t + 64] = (cnt > 0) ? m : 0.f;
    }
    __syncthreads();
    float acc = __ldg(bc1 + t);
#pragma unroll 8
    for (int j = 0; j < 128; j++) acc = fmaf(gv[j], Wc1[j * 64 + t], acc);
    float v = lrelu(acc) * __ldg(Wc2 + t);
#pragma unroll
    for (int o = 16; o > 0; o >>= 1) v += __shfl_down_sync(0xffffffffu, v, o);
    __shared__ float part[2];
    if ((t & 31) == 0) part[t >> 5] = v;
    __syncthreads();
    if (t == 0) out[g] = part[0] + part[1] + __ldg(bc2);
}

extern "C" void kernel_launch(void* const* d_in, const int* in_sizes, int n_in,
                              void* d_out, int out_size) {
    const float* x    = (const float*)d_in[0];
    const int*   ei   = (const int*)d_in[1];
    const int*   batch= (const int*)d_in[2];
    const float* W1   = (const float*)d_in[3];
    const float* b1   = (const float*)d_in[4];
    const float* W2   = (const float*)d_in[5];
    const float* b2   = (const float*)d_in[6];
    const float* W3   = (const float*)d_in[7];
    const float* b3   = (const float*)d_in[8];
    const float* W4   = (const float*)d_in[9];
    const float* b4   = (const float*)d_in[10];
    const float* Wc1  = (const float*)d_in[11];
    const float* bc1  = (const float*)d_in[12];
    const float* Wc2  = (const float*)d_in[13];
    const float* bc2  = (const float*)d_in[14];
    float* out = (float*)d_out;

    const int* src = ei;
    const int* dst = ei + NE;

    const int DSM_E = 49152;   // A/D 32K + B 16K
    const int DSM_N = 65536;
    cudaFuncSetAttribute(edge_mma_kernel<1>, cudaFuncAttributeMaxDynamicSharedMemorySize, DSM_E);
    cudaFuncSetAttribute(edge_mma_kernel<2>, cudaFuncAttributeMaxDynamicSharedMemorySize, DSM_E);
    cudaFuncSetAttribute(node_mlp64_mma, cudaFuncAttributeMaxDynamicSharedMemorySize, DSM_N);

    const int NB = (NN + 511) / 512;   // 98
    setup_kernel<<<3189, 256>>>(W2, W4, W3);
    hist_kernel<<<(NE + 255) / 256, 256>>>(dst);
    bscan_kernel<<<NB, 512>>>();
    topscan_kernel<<<1, 128>>>(NB);
    scatter_kernel<<<(NE + 255) / 256, 256>>>(src, dst);
    node_mlp6<<<(NN + 127) / 128, 128>>>(x, W1, b1);
    edge_mma_kernel<1><<<NCTA_E, 256, DSM_E>>>();
    node_mlp64_mma<<<(NN + 127) / 128, 128, DSM_N>>>(b3, b2);
    edge_mma_kernel<2><<<NCTA_E, 256, DSM_E>>>();
    pool_kernel<<<dim3(NG, 4), 256>>>(batch, b4);
    cls_kernel<<<NG, 64>>>(Wc1, bc1, Wc2, bc2, out);
}